// round 13
// baseline (speedup 1.0000x reference)
#include <cuda_runtime.h>
#include <cuda_bf16.h>
#include <math.h>
#include <stdint.h>

// ---------------- constants ----------------
#define BATCH 4
#define CH    128
#define HW    65536          // 256*256
#define WS    16
#define NWIN  256            // windows per batch (16x16)
#define CD    131            // cond channels
#define C4    32
#define C8    16

// ---------------- scratch (device globals; no allocation) ----------------
__device__ float g_cond[(size_t)BATCH * CD * HW];
__device__ float g_f   [(size_t)BATCH * C4 * HW];
__device__ float g_fmc [(size_t)BATCH * HW];
__device__ float g_fm  [BATCH * C4];
__device__ float g_ca  [BATCH * CH];
__device__ float g_off [(size_t)BATCH * 2 * HW];
__device__ float g_sa  [(size_t)BATCH * HW];
__device__ float g_mask[BATCH * NWIN];
__device__ float g_qw  [(size_t)BATCH * NWIN * 256 * CH];
__device__ float g_kw  [(size_t)BATCH * NWIN * 256 * CH];
__device__ float g_out [(size_t)BATCH * CH * HW];
__device__ float g_b1  [(size_t)BATCH * CH * HW];
__device__ float g_b2  [(size_t)BATCH * CH * HW];
__device__ __nv_bfloat16 g_whi [CH * CH];   // pq
__device__ __nv_bfloat16 g_wlo [CH * CH];
__device__ __nv_bfloat16 g_whi2[CH * CH];   // pk
__device__ __nv_bfloat16 g_wlo2[CH * CH];
__device__ __nv_bfloat16 g_whi3[CH * CH];   // cs1
__device__ __nv_bfloat16 g_wlo3[CH * CH];
__device__ __nv_bfloat16 g_whi4[CH * CH];   // po
__device__ __nv_bfloat16 g_wlo4[CH * CH];
__device__ __nv_bfloat16 g_whi5[CH * CH];   // pv
__device__ __nv_bfloat16 g_wlo5[CH * CH];
__device__ __nv_bfloat16 g_rwhi[C4 * CH];
__device__ __nv_bfloat16 g_rwlo[C4 * CH];

// =====================================================================
// mma.sync helpers
// =====================================================================
__device__ __forceinline__ uint32_t smem_u32(const void* p) {
    uint32_t a;
    asm("{ .reg .u64 t; cvta.to.shared.u64 t, %1; cvt.u32.u64 %0, t; }"
        : "=r"(a) : "l"(p));
    return a;
}

__device__ __forceinline__ void ldsm4(uint32_t& r0, uint32_t& r1, uint32_t& r2, uint32_t& r3,
                                      uint32_t addr) {
    asm volatile("ldmatrix.sync.aligned.m8n8.x4.shared.b16 {%0,%1,%2,%3}, [%4];"
                 : "=r"(r0), "=r"(r1), "=r"(r2), "=r"(r3) : "r"(addr));
}
__device__ __forceinline__ void ldsm4t(uint32_t& r0, uint32_t& r1, uint32_t& r2, uint32_t& r3,
                                       uint32_t addr) {
    asm volatile("ldmatrix.sync.aligned.m8n8.x4.trans.shared.b16 {%0,%1,%2,%3}, [%4];"
                 : "=r"(r0), "=r"(r1), "=r"(r2), "=r"(r3) : "r"(addr));
}

__device__ __forceinline__ void mma_bf16(float* d, const uint32_t* a, uint32_t b0, uint32_t b1) {
    asm volatile("mma.sync.aligned.m16n8k16.row.col.f32.bf16.bf16.f32 "
                 "{%0,%1,%2,%3},{%4,%5,%6,%7},{%8,%9},{%0,%1,%2,%3};"
                 : "+f"(d[0]), "+f"(d[1]), "+f"(d[2]), "+f"(d[3])
                 : "r"(a[0]), "r"(a[1]), "r"(a[2]), "r"(a[3]), "r"(b0), "r"(b1));
}

// swizzled smem offset for [row][k] bf16, 128 k per row (256B rows)
__device__ __forceinline__ uint32_t swz(int row, int k) {
    return (uint32_t)(row * 256 + ((((k >> 3) ^ (row & 7))) << 4) + ((k & 7) << 1));
}
// 256 k per row (512B rows)
__device__ __forceinline__ uint32_t swzP(int row, int k) {
    return (uint32_t)(row * 512 + (((k >> 3) ^ (row & 7)) << 4) + ((k & 7) << 1));
}
// 64 k per row (128B rows)
__device__ __forceinline__ uint32_t swzV(int row, int k) {
    return (uint32_t)(row * 128 + ((((k >> 3) & 7) ^ (row & 7)) << 4) + ((k & 7) << 1));
}

__device__ __forceinline__ uint32_t pack2(float a, float b) {
    __nv_bfloat162 t = __floats2bfloat162_rn(a, b);
    return *(uint32_t*)&t;
}

// ---------------- W pre-split kernels ----------------
__global__ __launch_bounds__(256) void w_prep(const float* __restrict__ W,
                                              __nv_bfloat16* __restrict__ Whi,
                                              __nv_bfloat16* __restrict__ Wlo)
{
    int i = blockIdx.x * 256 + threadIdx.x;
    float x = W[i];
    __nv_bfloat16 h = __float2bfloat16(x);
    Whi[i] = h;
    Wlo[i] = __float2bfloat16(x - __bfloat162float(h));
}

__global__ __launch_bounds__(256) void w_prep_rin(const float* __restrict__ W,
                                                  __nv_bfloat16* __restrict__ Whi,
                                                  __nv_bfloat16* __restrict__ Wlo)
{
    int i = blockIdx.x * 256 + threadIdx.x;      // 4096 threads
    int co = i >> 7, k = i & 127;
    float x = W[co * 131 + k];
    __nv_bfloat16 h = __float2bfloat16(x);
    Whi[i] = h;
    Wlo[i] = __float2bfloat16(x - __bfloat162float(h));
}

// =====================================================================
// Tensor-core (HMMA) 1x1 conv, N=64 px tile for 2 CTAs/SM occupancy.
// Numerics bit-identical to the N=128 version: same k-chunk/term order,
// same fragments, same epilogue adds.
// smem: W hi/lo 64KB + X hi/lo 32KB = 96KB.
// =====================================================================
#define CW_HI 0
#define CW_LO 32768
#define CX_HI 65536
#define CX_LO 81920
#define CONV_SMEM 98304
#define TPB_CONV 2

__global__ __launch_bounds__(256) void conv_mma(
    const float* __restrict__ In, long in_bstride,
    const __nv_bfloat16* __restrict__ Whi, const __nv_bfloat16* __restrict__ Wlo,
    const float* __restrict__ Bias,
    float* __restrict__ Out, long out_bstride)
{
    extern __shared__ char smc[];
    uint32_t sbase = smem_u32(smc);
    int tid = threadIdx.x, lane = tid & 31, wid = tid >> 5;
    int wm = wid & 3, wn = wid >> 2;          // warp tile: 32 m x 32 n
    int g = lane >> 2, q = lane & 3;

    // ---- load W hi/lo into swizzled smem [co][k] (256B rows) ----
    for (int idx = tid; idx < 2048; idx += 256) {
        int co = idx >> 4, ch = idx & 15;
        uint32_t off = (uint32_t)co * 256u + (uint32_t)((ch ^ (co & 7)) << 4);
        *(uint4*)(smc + CW_HI + off) = ((const uint4*)Whi)[idx];
        *(uint4*)(smc + CW_LO + off) = ((const uint4*)Wlo)[idx];
    }

    for (int t = 0; t < TPB_CONV; t++) {
        int tile = blockIdx.x * TPB_CONV + t;
        int b = tile >> 10;                   // 1024 tiles of 64px per batch
        int p0 = (tile & 1023) << 6;
        const float* inb = In + (long)b * in_bstride + p0;

        __syncthreads();   // X free from previous tile; W visible on t=0

        // ---- convert X tile: In[k][p0+px] -> Xsm[k][px] hi/lo (128B rows) ----
#pragma unroll
        for (int it = 0; it < 8; it++) {
            int idx = it * 256 + tid;         // 0..2047
            int k = idx >> 4, pxg = idx & 15;
            float4 v = *(const float4*)(inb + (long)k * HW + pxg * 4);
            __nv_bfloat16 h0 = __float2bfloat16(v.x), h1 = __float2bfloat16(v.y);
            __nv_bfloat16 h2 = __float2bfloat16(v.z), h3 = __float2bfloat16(v.w);
            uint2 hi, lo;
            hi.x = pack2(__bfloat162float(h0), __bfloat162float(h1));
            hi.y = pack2(__bfloat162float(h2), __bfloat162float(h3));
            lo.x = pack2(v.x - __bfloat162float(h0), v.y - __bfloat162float(h1));
            lo.y = pack2(v.z - __bfloat162float(h2), v.w - __bfloat162float(h3));
            int px = pxg * 4;
            uint32_t off = (uint32_t)k * 128u
                         + (uint32_t)((((px >> 3) ^ (k & 7))) << 4)
                         + (uint32_t)((px & 7) << 1);
            *(uint2*)(smc + CX_HI + off) = hi;
            *(uint2*)(smc + CX_LO + off) = lo;
        }
        __syncthreads();

        // ---- compute: 3 terms x 8 k-steps ----
        int jmat = lane >> 3, jrow = lane & 7;
        float acc[2][4][4] = {};
#pragma unroll
        for (int term = 0; term < 3; term++) {
            uint32_t a_base = sbase + (term == 2 ? CW_LO : CW_HI);
            uint32_t b_base = sbase + (term == 1 ? CX_LO : CX_HI);
#pragma unroll
            for (int k0 = 0; k0 < 128; k0 += 16) {
                int kk = k0 + ((lane >> 4) << 3);
                uint32_t a[2][4];
#pragma unroll
                for (int mf = 0; mf < 2; mf++)
                    ldsm4(a[mf][0], a[mf][1], a[mf][2], a[mf][3],
                          a_base + swz(wm * 32 + mf * 16 + (lane & 15), kk));
                int kr = k0 + ((jmat & 1) << 3) + jrow;
#pragma unroll
                for (int nb = 0; nb < 2; nb++) {
                    int nn = wn * 32 + nb * 16 + ((jmat >> 1) << 3);
                    uint32_t addr = b_base + (uint32_t)kr * 128u
                                  + (uint32_t)((((nn >> 3) ^ (kr & 7))) << 4);
                    uint32_t bf[4];
                    ldsm4t(bf[0], bf[1], bf[2], bf[3], addr);
#pragma unroll
                    for (int mf = 0; mf < 2; mf++) {
                        mma_bf16(acc[mf][nb * 2 + 0], a[mf], bf[0], bf[1]);
                        mma_bf16(acc[mf][nb * 2 + 1], a[mf], bf[2], bf[3]);
                    }
                }
            }
        }

        // ---- epilogue: coalesced NCHW float2 stores ----
        float* ob = Out + (long)b * out_bstride;
#pragma unroll
        for (int mf = 0; mf < 2; mf++) {
            int co0 = wm * 32 + mf * 16 + g;
            float bv0 = Bias[co0], bv1 = Bias[co0 + 8];
            float* r0 = ob + (long)co0 * HW + p0;
            float* r1 = ob + (long)(co0 + 8) * HW + p0;
#pragma unroll
            for (int nf = 0; nf < 4; nf++) {
                int col = wn * 32 + nf * 8 + q * 2;
                float2 v0 = {acc[mf][nf][0] + bv0, acc[mf][nf][1] + bv0};
                float2 v1 = {acc[mf][nf][2] + bv1, acc[mf][nf][3] + bv1};
                *(float2*)(r0 + col) = v0;
                *(float2*)(r1 + col) = v1;
            }
        }
    }
}

// =====================================================================
// rin HMMA conv (validated R8 kernel, unchanged)
// =====================================================================
#define RW_HI 0
#define RW_LO 8192
#define RX_HI 16384
#define RX_LO 49152
#define RIN_SMEM 81920
#define TPB_RIN 2

__global__ __launch_bounds__(256) void rin_mma(
    const float* __restrict__ cond,
    const float* __restrict__ cg,
    const float* __restrict__ rw,
    const __nv_bfloat16* __restrict__ Whi, const __nv_bfloat16* __restrict__ Wlo,
    const float* __restrict__ Bias,
    float* __restrict__ Out)
{
    extern __shared__ char smc[];
    uint32_t sbase = smem_u32(smc);
    int tid = threadIdx.x, lane = tid & 31, wid = tid >> 5;
    int wm = wid & 1, wn = wid >> 1;
    int g = lane >> 2, q = lane & 3;

    for (int idx = tid; idx < 512; idx += 256) {
        int co = idx >> 4, ch = idx & 15;
        uint32_t off = (uint32_t)co * 256u + (uint32_t)((ch ^ (co & 7)) << 4);
        *(uint4*)(smc + RW_HI + off) = ((const uint4*)Whi)[idx];
        *(uint4*)(smc + RW_LO + off) = ((const uint4*)Wlo)[idx];
    }

    for (int t = 0; t < TPB_RIN; t++) {
        int tile = blockIdx.x * TPB_RIN + t;
        int b = tile >> 9;
        int p0 = (tile & 511) << 7;
        const float* inb = cond + (long)b * CD * HW + p0;

        __syncthreads();

#pragma unroll 4
        for (int it = 0; it < 16; it++) {
            int k = wid * 16 + it;
            float4 v = *(const float4*)(inb + (long)k * HW + lane * 4);
            __nv_bfloat16 h0 = __float2bfloat16(v.x), h1 = __float2bfloat16(v.y);
            __nv_bfloat16 h2 = __float2bfloat16(v.z), h3 = __float2bfloat16(v.w);
            uint2 hi, lo;
            hi.x = pack2(__bfloat162float(h0), __bfloat162float(h1));
            hi.y = pack2(__bfloat162float(h2), __bfloat162float(h3));
            lo.x = pack2(v.x - __bfloat162float(h0), v.y - __bfloat162float(h1));
            lo.y = pack2(v.z - __bfloat162float(h2), v.w - __bfloat162float(h3));
            uint32_t off = (uint32_t)k * 256u
                         + (uint32_t)((((lane >> 1) ^ (k & 7))) << 4)
                         + (uint32_t)((lane & 1) << 3);
            *(uint2*)(smc + RX_HI + off) = hi;
            *(uint2*)(smc + RX_LO + off) = lo;
        }
        __syncthreads();

        int jmat = lane >> 3, jrow = lane & 7;
        float acc[4][4] = {};
#pragma unroll
        for (int term = 0; term < 3; term++) {
            uint32_t a_base = sbase + (term == 2 ? RW_LO : RW_HI);
            uint32_t b_base = sbase + (term == 1 ? RX_LO : RX_HI);
#pragma unroll
            for (int k0 = 0; k0 < 128; k0 += 16) {
                int kk = k0 + ((lane >> 4) << 3);
                uint32_t a[4];
                ldsm4(a[0], a[1], a[2], a[3],
                      a_base + swz(wm * 16 + (lane & 15), kk));
                int kr = k0 + ((jmat & 1) << 3) + jrow;
#pragma unroll
                for (int nb = 0; nb < 2; nb++) {
                    int nn = wn * 32 + nb * 16 + ((jmat >> 1) << 3);
                    uint32_t addr = b_base + (uint32_t)kr * 256u
                                  + (uint32_t)((((nn >> 3) ^ (kr & 7))) << 4);
                    uint32_t bf[4];
                    ldsm4t(bf[0], bf[1], bf[2], bf[3], addr);
                    mma_bf16(acc[nb * 2 + 0], a, bf[0], bf[1]);
                    mma_bf16(acc[nb * 2 + 1], a, bf[2], bf[3]);
                }
            }
        }

        int co0 = wm * 16 + g;
        int co1 = co0 + 8;
        float bv0 = Bias[co0], bv1 = Bias[co1];
        float wa0 = rw[co0 * 131 + 128], wa1 = rw[co0 * 131 + 129], wa2 = rw[co0 * 131 + 130];
        float wb0 = rw[co1 * 131 + 128], wb1 = rw[co1 * 131 + 129], wb2 = rw[co1 * 131 + 130];
        const float* cgb = cg + (long)b * HW;
        float* ob = Out + (long)b * C4 * HW;
#pragma unroll
        for (int nf = 0; nf < 4; nf++) {
#pragma unroll
            for (int e = 0; e < 2; e++) {
                int px = wn * 32 + nf * 8 + q * 2 + e;
                int p = p0 + px;
                int hh = p >> 8, ww = p & 255;
                float ly = -1.f + (2.f / 15.f) * (float)(hh & 15);
                float lx = -1.f + (2.f / 15.f) * (float)(ww & 15);
                float cgv = cgb[p];
                float v0 = acc[nf][e]     + bv0 + wa0 * cgv + wa1 * ly + wa2 * lx;
                float v1 = acc[nf][e + 2] + bv1 + wb0 * cgv + wb1 * ly + wb2 * lx;
                v0 = v0 > 0.f ? v0 : 0.2f * v0;
                v1 = v1 > 0.f ? v1 : 0.2f * v1;
                ob[(long)co0 * HW + p] = v0;
                ob[(long)co1 * HW + p] = v1;
            }
        }
    }
}

// =====================================================================
// Fused warp + q-proj + k-proj (validated R7 kernel, unchanged)
// =====================================================================
#define QW_HI 0
#define QW_LO 32768
#define KW_HI 65536
#define KW_LO 98304
#define QX_HI 131072
#define QX_LO 163840
#define QSTG  131072
#define QPRM  196608
#define QK_SMEM 200704

__global__ __launch_bounds__(256) void convqk_mma(
    const float* __restrict__ x,
    const __nv_bfloat16* __restrict__ Wqhi, const __nv_bfloat16* __restrict__ Wqlo,
    const __nv_bfloat16* __restrict__ Wkhi, const __nv_bfloat16* __restrict__ Wklo,
    const float* __restrict__ Bq, const float* __restrict__ Bk)
{
    extern __shared__ char smc[];
    uint32_t sbase = smem_u32(smc);
    int tid = threadIdx.x, lane = tid & 31, wid = tid >> 5;
    int wm = wid & 3, wn = wid >> 2;
    int g = lane >> 2, q = lane & 3;

    int*   i00s = (int*)(smc + QPRM);
    int*   i01s = i00s + 128;
    int*   i10s = i00s + 256;
    int*   i11s = i00s + 384;
    float* w00s = (float*)(i00s + 512);
    float* w01s = w00s + 128;
    float* w10s = w00s + 256;
    float* w11s = w00s + 384;

    for (int idx = tid; idx < 2048; idx += 256) {
        int co = idx >> 4, ch = idx & 15;
        uint32_t off = (uint32_t)co * 256u + (uint32_t)((ch ^ (co & 7)) << 4);
        *(uint4*)(smc + QW_HI + off) = ((const uint4*)Wqhi)[idx];
        *(uint4*)(smc + QW_LO + off) = ((const uint4*)Wqlo)[idx];
        *(uint4*)(smc + KW_HI + off) = ((const uint4*)Wkhi)[idx];
        *(uint4*)(smc + KW_LO + off) = ((const uint4*)Wklo)[idx];
    }

    for (int t = 0; t < 2; t++) {
        int tile = blockIdx.x * 2 + t;
        int b = tile >> 9;
        int p0 = (tile & 511) << 7;

        __syncthreads();

        if (tid < 128) {
            int p = p0 + tid;
            int h = p >> 8, w = p & 255;
            float fx = g_off[(long)b * 2 * HW + p];
            float fy = g_off[(long)b * 2 * HW + HW + p];
            float sx = fminf(fmaxf((float)w + fx, 0.f), 255.f);
            float sy = fminf(fmaxf((float)h + fy, 0.f), 255.f);
            float x0f = floorf(sx), y0f = floorf(sy);
            float x1f = fminf(x0f + 1.f, 255.f), y1f = fminf(y0f + 1.f, 255.f);
            float wx = sx - x0f, wy = sy - y0f;
            int x0 = (int)x0f, x1 = (int)x1f, y0 = (int)y0f, y1 = (int)y1f;
            i00s[tid] = y0 * 256 + x0; i01s[tid] = y0 * 256 + x1;
            i10s[tid] = y1 * 256 + x0; i11s[tid] = y1 * 256 + x1;
            w00s[tid] = (1.f - wx) * (1.f - wy); w01s[tid] = wx * (1.f - wy);
            w10s[tid] = (1.f - wx) * wy;         w11s[tid] = wx * wy;
        }
        __syncthreads();

        {
            int4  I00 = ((const int4*)i00s)[lane], I01 = ((const int4*)i01s)[lane];
            int4  I10 = ((const int4*)i10s)[lane], I11 = ((const int4*)i11s)[lane];
            float4 W00 = ((const float4*)w00s)[lane], W01 = ((const float4*)w01s)[lane];
            float4 W10 = ((const float4*)w10s)[lane], W11 = ((const float4*)w11s)[lane];
            const float* xb = x + (long)b * CH * HW;
#pragma unroll 4
            for (int it = 0; it < 16; it++) {
                int k = wid * 16 + it;
                const float* xc = xb + (long)k * HW;
                float vv[4];
                vv[0] = W00.x * xc[I00.x] + W01.x * xc[I01.x] + W10.x * xc[I10.x] + W11.x * xc[I11.x];
                vv[1] = W00.y * xc[I00.y] + W01.y * xc[I01.y] + W10.y * xc[I10.y] + W11.y * xc[I11.y];
                vv[2] = W00.z * xc[I00.z] + W01.z * xc[I01.z] + W10.z * xc[I10.z] + W11.z * xc[I11.z];
                vv[3] = W00.w * xc[I00.w] + W01.w * xc[I01.w] + W10.w * xc[I10.w] + W11.w * xc[I11.w];
                __nv_bfloat16 h0 = __float2bfloat16(vv[0]), h1 = __float2bfloat16(vv[1]);
                __nv_bfloat16 h2 = __float2bfloat16(vv[2]), h3 = __float2bfloat16(vv[3]);
                uint2 hi, lo;
                hi.x = pack2(__bfloat162float(h0), __bfloat162float(h1));
                hi.y = pack2(__bfloat162float(h2), __bfloat162float(h3));
                lo.x = pack2(vv[0] - __bfloat162float(h0), vv[1] - __bfloat162float(h1));
                lo.y = pack2(vv[2] - __bfloat162float(h2), vv[3] - __bfloat162float(h3));
                uint32_t off = (uint32_t)k * 256u
                             + (uint32_t)((((lane >> 1) ^ (k & 7))) << 4)
                             + (uint32_t)((lane & 1) << 3);
                *(uint2*)(smc + QX_HI + off) = hi;
                *(uint2*)(smc + QX_LO + off) = lo;
            }
        }
        __syncthreads();

        int jmat = lane >> 3, jrow = lane & 7;
        float accq[2][8][4] = {};
        float acck[2][8][4] = {};
#pragma unroll
        for (int term = 0; term < 3; term++) {
            uint32_t aq_base = sbase + (term == 2 ? QW_LO : QW_HI);
            uint32_t ak_base = sbase + (term == 2 ? KW_LO : KW_HI);
            uint32_t b_base  = sbase + (term == 1 ? QX_LO : QX_HI);
#pragma unroll
            for (int k0 = 0; k0 < 128; k0 += 16) {
                int kk = k0 + ((lane >> 4) << 3);
                uint32_t aq[2][4], ak[2][4];
#pragma unroll
                for (int mf = 0; mf < 2; mf++) {
                    ldsm4(aq[mf][0], aq[mf][1], aq[mf][2], aq[mf][3],
                          aq_base + swz(wm * 32 + mf * 16 + (lane & 15), kk));
                    ldsm4(ak[mf][0], ak[mf][1], ak[mf][2], ak[mf][3],
                          ak_base + swz(wm * 32 + mf * 16 + (lane & 15), kk));
                }
                int kr = k0 + ((jmat & 1) << 3) + jrow;
#pragma unroll
                for (int nb = 0; nb < 4; nb++) {
                    int nn = wn * 64 + nb * 16 + ((jmat >> 1) << 3);
                    uint32_t addr = b_base + (uint32_t)kr * 256u
                                  + (uint32_t)((((nn >> 3) ^ (kr & 7))) << 4);
                    uint32_t bf[4];
                    ldsm4t(bf[0], bf[1], bf[2], bf[3], addr);
#pragma unroll
                    for (int mf = 0; mf < 2; mf++) {
                        mma_bf16(accq[mf][nb * 2 + 0], aq[mf], bf[0], bf[1]);
                        mma_bf16(accq[mf][nb * 2 + 1], aq[mf], bf[2], bf[3]);
                        mma_bf16(acck[mf][nb * 2 + 0], ak[mf], bf[0], bf[1]);
                        mma_bf16(acck[mf][nb * 2 + 1], ak[mf], bf[2], bf[3]);
                    }
                }
            }
        }

        float* St = (float*)(smc + QSTG);
        __syncthreads();
#pragma unroll
        for (int mf = 0; mf < 2; mf++) {
            int co0 = wm * 32 + mf * 16 + g;
            uint32_t perm = (uint32_t)(q << 3);
#pragma unroll
            for (int nf = 0; nf < 8; nf++) {
                int px = wn * 64 + nf * 8 + q * 2;
                St[px * 128 + (co0 ^ perm)]             = accq[mf][nf][0];
                St[(px + 1) * 128 + (co0 ^ perm)]       = accq[mf][nf][1];
                St[px * 128 + ((co0 + 8) ^ perm)]       = accq[mf][nf][2];
                St[(px + 1) * 128 + ((co0 + 8) ^ perm)] = accq[mf][nf][3];
            }
        }
        __syncthreads();
#pragma unroll
        for (int it = 0; it < 16; it++) {
            int idx = it * 256 + tid;
            int px = idx >> 5, cc = (idx & 31) * 4;
            uint32_t perm = (uint32_t)(((px >> 1) & 3) << 3);
            float4 vv = *(float4*)(St + px * 128 + (cc ^ perm));
            float4 bb = *(const float4*)(Bq + cc);
            vv.x += bb.x; vv.y += bb.y; vv.z += bb.z; vv.w += bb.w;
            int p = p0 + px;
            int h = p >> 8, w = p & 255;
            long a0 = ((long)(b * NWIN + (h >> 4) * 16 + (w >> 4)) * 256
                       + (h & 15) * 16 + (w & 15)) * CH + cc;
            *(float4*)(g_qw + a0) = vv;
        }
        __syncthreads();
#pragma unroll
        for (int mf = 0; mf < 2; mf++) {
            int co0 = wm * 32 + mf * 16 + g;
            uint32_t perm = (uint32_t)(q << 3);
#pragma unroll
            for (int nf = 0; nf < 8; nf++) {
                int px = wn * 64 + nf * 8 + q * 2;
                St[px * 128 + (co0 ^ perm)]             = acck[mf][nf][0];
                St[(px + 1) * 128 + (co0 ^ perm)]       = acck[mf][nf][1];
                St[px * 128 + ((co0 + 8) ^ perm)]       = acck[mf][nf][2];
                St[(px + 1) * 128 + ((co0 + 8) ^ perm)] = acck[mf][nf][3];
            }
        }
        __syncthreads();
#pragma unroll
        for (int it = 0; it < 16; it++) {
            int idx = it * 256 + tid;
            int px = idx >> 5, cc = (idx & 31) * 4;
            uint32_t perm = (uint32_t)(((px >> 1) & 3) << 3);
            float4 vv = *(float4*)(St + px * 128 + (cc ^ perm));
            float4 bb = *(const float4*)(Bk + cc);
            vv.x += bb.x; vv.y += bb.y; vv.z += bb.z; vv.w += bb.w;
            int p = p0 + px;
            int h = p >> 8, w = p & 255;
            long a0 = ((long)(b * NWIN + (h >> 4) * 16 + (w >> 4)) * 256
                       + (h & 15) * 16 + (w & 15)) * CH + cc;
            *(float4*)(g_kw + a0) = vv;
        }
    }
}

// =====================================================================
// Fused window attention (validated R6 kernel, unchanged)
// =====================================================================
#define AT_QHI 0
#define AT_QLO 16384
#define AT_KHI 32768
#define AT_KLO 49152
#define AT_PHI 0
#define AT_PLO 32768
#define AT_S   65536
#define AT_SROW 260
#define AT_S2  65536
#define AT_VHI 132096
#define AT_VLO 148480
#define AT_SMEM 164864

__global__ __launch_bounds__(256) void attn_kernel()
{
    int win = blockIdx.y;
    int i0 = blockIdx.x * 64;
    int b = win >> 8, n = win & 255;
    int wy = n >> 4, wx = n & 15;
    const float* vbase = g_cond + (long)b * CD * HW;
    int tid = threadIdx.x, lane = tid & 31, wid = tid >> 5;

    if (g_mask[win] == 0.f) {
        const float* sab = g_sa + (long)b * HW;
        float* ob = g_out + (long)b * CH * HW;
#pragma unroll 4
        for (int it = 0; it < 32; it++) {
            int idx = it * 256 + tid;
            int c = idx >> 6, pxl = idx & 63;
            int i = i0 + pxl;
            int p = (wy * 16 + (i >> 4)) * 256 + wx * 16 + (i & 15);
            ob[(long)c * HW + p] = vbase[(long)c * HW + p] * sab[p];
        }
        return;
    }

    extern __shared__ char smc[];
    uint32_t sbase = smem_u32(smc);
    int wm = wid & 3, wn = wid >> 2;
    int g = lane >> 2, q = lane & 3;

    {
        const float* Qg = g_qw + ((long)win * 256 + i0) * CH;
#pragma unroll
        for (int it = 0; it < 8; it++) {
            int e = it * 256 + tid;
            int row = e >> 5, k = (e & 31) * 4;
            float4 v = *(const float4*)(Qg + row * CH + k);
            __nv_bfloat16 h0 = __float2bfloat16(v.x), h1 = __float2bfloat16(v.y);
            __nv_bfloat16 h2 = __float2bfloat16(v.z), h3 = __float2bfloat16(v.w);
            uint2 hi, lo;
            hi.x = pack2(__bfloat162float(h0), __bfloat162float(h1));
            hi.y = pack2(__bfloat162float(h2), __bfloat162float(h3));
            lo.x = pack2(v.x - __bfloat162float(h0), v.y - __bfloat162float(h1));
            lo.y = pack2(v.z - __bfloat162float(h2), v.w - __bfloat162float(h3));
            uint32_t off = swz(row, k);
            *(uint2*)(smc + AT_QHI + off) = hi;
            *(uint2*)(smc + AT_QLO + off) = lo;
        }
    }

    float* Ssm = (float*)(smc + AT_S);
    for (int kc = 0; kc < 4; kc++) {
        __syncthreads();
        const float* Kg = g_kw + ((long)win * 256 + kc * 64) * CH;
#pragma unroll
        for (int it = 0; it < 8; it++) {
            int e = it * 256 + tid;
            int row = e >> 5, k = (e & 31) * 4;
            float4 v = *(const float4*)(Kg + row * CH + k);
            __nv_bfloat16 h0 = __float2bfloat16(v.x), h1 = __float2bfloat16(v.y);
            __nv_bfloat16 h2 = __float2bfloat16(v.z), h3 = __float2bfloat16(v.w);
            uint2 hi, lo;
            hi.x = pack2(__bfloat162float(h0), __bfloat162float(h1));
            hi.y = pack2(__bfloat162float(h2), __bfloat162float(h3));
            lo.x = pack2(v.x - __bfloat162float(h0), v.y - __bfloat162float(h1));
            lo.y = pack2(v.z - __bfloat162float(h2), v.w - __bfloat162float(h3));
            uint32_t off = swz(row, k);
            *(uint2*)(smc + AT_KHI + off) = hi;
            *(uint2*)(smc + AT_KLO + off) = lo;
        }
        __syncthreads();

        float acc[4][4] = {};
#pragma unroll
        for (int term = 0; term < 3; term++) {
            uint32_t a_base = sbase + (term == 2 ? AT_QLO : AT_QHI);
            uint32_t b_base = sbase + (term == 1 ? AT_KLO : AT_KHI);
#pragma unroll
            for (int k0 = 0; k0 < 128; k0 += 16) {
                int kk = k0 + ((lane >> 4) << 3);
                uint32_t a[4];
                ldsm4(a[0], a[1], a[2], a[3],
                      a_base + swz(wm * 16 + (lane & 15), kk));
#pragma unroll
                for (int nb = 0; nb < 2; nb++) {
                    uint32_t bf[4];
                    ldsm4(bf[0], bf[1], bf[2], bf[3],
                          b_base + swz(wn * 32 + nb * 16 + (lane & 15), kk));
                    mma_bf16(acc[nb * 2 + 0], a, bf[0], bf[2]);
                    mma_bf16(acc[nb * 2 + 1], a, bf[1], bf[3]);
                }
            }
        }
        int srow = wm * 16 + g;
        int scol0 = kc * 64 + wn * 32;
#pragma unroll
        for (int nf = 0; nf < 4; nf++) {
            int col = scol0 + nf * 8 + q * 2;
            Ssm[srow * AT_SROW + col]           = acc[nf][0];
            Ssm[srow * AT_SROW + col + 1]       = acc[nf][1];
            Ssm[(srow + 8) * AT_SROW + col]     = acc[nf][2];
            Ssm[(srow + 8) * AT_SROW + col + 1] = acc[nf][3];
        }
    }
    __syncthreads();

    for (int r = wid; r < 64; r += 8) {
        float v[8];
        float mx = -1e30f;
#pragma unroll
        for (int kk = 0; kk < 8; kk++) { v[kk] = Ssm[r * AT_SROW + lane + 32 * kk]; mx = fmaxf(mx, v[kk]); }
#pragma unroll
        for (int o = 16; o > 0; o >>= 1) mx = fmaxf(mx, __shfl_xor_sync(0xffffffffu, mx, o));
        float s = 0.f;
#pragma unroll
        for (int kk = 0; kk < 8; kk++) { v[kk] = expf(v[kk] - mx); s += v[kk]; }
#pragma unroll
        for (int o = 16; o > 0; o >>= 1) s += __shfl_xor_sync(0xffffffffu, s, o);
        float inv = 1.f / s;
#pragma unroll
        for (int kk = 0; kk < 8; kk++) {
            float pv = v[kk] * inv;
            __nv_bfloat16 h = __float2bfloat16(pv);
            __nv_bfloat16 l = __float2bfloat16(pv - __bfloat162float(h));
            uint32_t off = swzP(r, lane + 32 * kk);
            *(__nv_bfloat16*)(smc + AT_PHI + off) = h;
            *(__nv_bfloat16*)(smc + AT_PLO + off) = l;
        }
    }

    float oacc[8][4] = {};
    for (int kc = 0; kc < 4; kc++) {
        __syncthreads();
#pragma unroll 4
        for (int it = 0; it < 32; it++) {
            int idx = it * 256 + tid;
            int c = idx >> 6, jl = idx & 63;
            int j = kc * 64 + jl;
            int p = (wy * 16 + (j >> 4)) * 256 + wx * 16 + (j & 15);
            float xv = vbase[(long)c * HW + p];
            __nv_bfloat16 h = __float2bfloat16(xv);
            __nv_bfloat16 l = __float2bfloat16(xv - __bfloat162float(h));
            uint32_t off = swzV(c, jl);
            *(__nv_bfloat16*)(smc + AT_VHI + off) = h;
            *(__nv_bfloat16*)(smc + AT_VLO + off) = l;
        }
        __syncthreads();
#pragma unroll
        for (int term = 0; term < 3; term++) {
            uint32_t a_base = sbase + (term == 2 ? AT_PLO : AT_PHI);
            uint32_t b_base = sbase + (term == 1 ? AT_VLO : AT_VHI);
#pragma unroll
            for (int ks = 0; ks < 64; ks += 16) {
                int kk = ks + ((lane >> 4) << 3);
                uint32_t a[4];
                ldsm4(a[0], a[1], a[2], a[3],
                      a_base + swzP(wm * 16 + (lane & 15), kc * 64 + kk));
#pragma unroll
                for (int nb = 0; nb < 4; nb++) {
                    uint32_t bf[4];
                    ldsm4(bf[0], bf[1], bf[2], bf[3],
                          b_base + swzV(wn * 64 + nb * 16 + (lane & 15), kk));
                    mma_bf16(oacc[nb * 2 + 0], a, bf[0], bf[2]);
                    mma_bf16(oacc[nb * 2 + 1], a, bf[1], bf[3]);
                }
            }
        }
    }

    __syncthreads();
    float* S2 = (float*)(smc + AT_S2);
    {
        int prow = wm * 16 + g;
#pragma unroll
        for (int nf = 0; nf < 8; nf++) {
            int ch = wn * 64 + nf * 8 + q * 2;
            S2[ch * 68 + prow]           = oacc[nf][0];
            S2[(ch + 1) * 68 + prow]     = oacc[nf][1];
            S2[ch * 68 + prow + 8]       = oacc[nf][2];
            S2[(ch + 1) * 68 + prow + 8] = oacc[nf][3];
        }
    }
    __syncthreads();
    {
        float* ob = g_out + (long)b * CH * HW;
#pragma unroll 4
        for (int it = 0; it < 32; it++) {
            int idx = it * 256 + tid;
            int c = idx >> 6, pxl = idx & 63;
            int i = i0 + pxl;
            int p = (wy * 16 + (i >> 4)) * 256 + wx * 16 + (i & 15);
            ob[(long)c * HW + p] = S2[c * 68 + pxl];
        }
    }
}

// ---------------- offsets head ----------------
__global__ __launch_bounds__(256) void roff_kernel(
    const float* __restrict__ w1, const float* __restrict__ b1,
    const float* __restrict__ w2, const float* __restrict__ b2)
{
    __shared__ float W1[16 * 32], B1[16], W2[2 * 16], B2[2];
    int t = threadIdx.x;
    for (int i = t; i < 512; i += 256) W1[i] = w1[i];
    if (t < 16) B1[t] = b1[t];
    if (t < 32) W2[t] = w2[t];
    if (t < 2)  B2[t] = b2[t];
    __syncthreads();
    int idx = blockIdx.x * 256 + t;
    int b = idx >> 16, p = idx & 65535;
    float fv[32];
    const float* fb = g_f + (long)b * C4 * HW + p;
#pragma unroll
    for (int c = 0; c < 32; c++) fv[c] = fb[(long)c * HW];
    float o0 = B2[0], o1 = B2[1];
#pragma unroll
    for (int o = 0; o < 16; o++) {
        float h = B1[o];
#pragma unroll
        for (int c = 0; c < 32; c++) h += W1[o * 32 + c] * fv[c];
        h = h > 0.f ? h : 0.2f * h;
        o0 += W2[o] * h;
        o1 += W2[16 + o] * h;
    }
    g_off[(long)b * 2 * HW + p]      = o0;
    g_off[(long)b * 2 * HW + HW + p] = o1;
}

// ---------------- channel-mean of f ----------------
__global__ __launch_bounds__(256) void fmc_kernel()
{
    int idx = blockIdx.x * 256 + threadIdx.x;
    int b = idx >> 16, p = idx & 65535;
    const float* fb = g_f + (long)b * C4 * HW + p;
    float s = 0.f;
#pragma unroll
    for (int c = 0; c < 32; c++) s += fb[(long)c * HW];
    g_fmc[idx] = s * (1.f / 32.f);
}

// ---------------- spatial mean of f ----------------
__global__ __launch_bounds__(256) void fm_kernel()
{
    int bc = blockIdx.x;
    const float* src = g_f + (long)bc * HW;
    float s = 0.f;
    for (int i = threadIdx.x; i < HW; i += 256) s += src[i];
    __shared__ float red[256];
    red[threadIdx.x] = s; __syncthreads();
    for (int st = 128; st > 0; st >>= 1) {
        if (threadIdx.x < st) red[threadIdx.x] += red[threadIdx.x + st];
        __syncthreads();
    }
    if (threadIdx.x == 0) g_fm[bc] = red[0] * (1.f / 65536.f);
}

__global__ void ca_kernel(const float* __restrict__ w, const float* __restrict__ bias)
{
    int t = threadIdx.x;
    int b = t >> 7, co = t & 127;
    float a = bias[co];
#pragma unroll
    for (int k = 0; k < 32; k++) a += w[co * 32 + k] * g_fm[b * 32 + k];
    g_ca[t] = 1.f / (1.f + expf(-a));
}

// ---------------- spatial attention ----------------
__global__ __launch_bounds__(256) void sa_kernel(const float* __restrict__ w, const float* __restrict__ bias)
{
    __shared__ float Wsm[32 * 9];
    for (int i = threadIdx.x; i < 288; i += 256) Wsm[i] = w[i];
    __syncthreads();
    int idx = blockIdx.x * 256 + threadIdx.x;
    int b = idx >> 16, p = idx & 65535;
    int h = p >> 8, wc = p & 255;
    float acc = bias[0];
    const float* fb = g_f + (long)b * C4 * HW;
    for (int c = 0; c < 32; c++) {
        const float* fc = fb + (long)c * HW;
#pragma unroll
        for (int kh = 0; kh < 3; kh++) {
            int hh = h + kh - 1;
            if ((unsigned)hh >= 256u) continue;
#pragma unroll
            for (int kw = 0; kw < 3; kw++) {
                int ww = wc + kw - 1;
                if ((unsigned)ww >= 256u) continue;
                acc += fc[hh * 256 + ww] * Wsm[c * 9 + kh * 3 + kw];
            }
        }
    }
    g_sa[idx] = 1.f / (1.f + expf(-acc));
}

// ---------------- window mask ----------------
__global__ __launch_bounds__(256) void mask_kernel(
    const float* __restrict__ rm1w, const float* __restrict__ rm1b,
    const float* __restrict__ rm2w, const float* __restrict__ rm2b,
    const float* __restrict__ gu)
{
    __shared__ float mw[256];
    __shared__ float hs[16];
    int win = blockIdx.x;
    int b = win >> 8, n = win & 255;
    int wy = n >> 4, wx = n & 15;
    int e = threadIdx.x;
    int dh = e >> 4, dw = e & 15;
    int p = (wy * 16 + dh) * 256 + wx * 16 + dw;
    mw[e] = g_fmc[(long)b * HW + p];
    __syncthreads();
    if (e < 16) {
        float h = rm1b[e];
        for (int k = 0; k < 256; k++) h += rm1w[e * 256 + k] * mw[k];
        hs[e] = h > 0.f ? h : 0.2f * h;
    }
    __syncthreads();
    if (e == 0) {
        float l0 = rm2b[0], l1 = rm2b[1];
#pragma unroll
        for (int k = 0; k < 16; k++) { l0 += rm2w[k] * hs[k]; l1 += rm2w[16 + k] * hs[k]; }
        float m = fmaxf(l0, l1);
        float p0 = expf(l0 - m), p1 = expf(l1 - m);
        float s = p0 + p1; p0 /= s; p1 /= s;
        float u0 = gu[(long)win * 2 + 0], u1 = gu[(long)win * 2 + 1];
        float q0 = -logf(-logf(u0 + 1e-10f) + 1e-10f);
        float q1 = -logf(-logf(u1 + 1e-10f) + 1e-10f);
        g_mask[win] = (p0 + q0 >= p1 + q1) ? 1.f : 0.f;
    }
}

// =====================================================================
// Smem-tiled depthwise 5x5 (validated R10 kernel)
// =====================================================================
__global__ __launch_bounds__(256) void dw5_tiled(
    const float* __restrict__ In, const float* __restrict__ Wt,
    const float* __restrict__ Bias, float* __restrict__ Out,
    int dil, int fuse_gelu)
{
    __shared__ float Fs[44][44];
    __shared__ float Wsm[25];
    int blk = blockIdx.x;
    int tile = blk & 63;
    int bc = blk >> 6;
    int c = bc & 127;
    int ty0 = (tile >> 3) * 32, tx0 = (tile & 7) * 32;
    int tid = threadIdx.x;
    int halo = 2 * dil;
    int tdim = 32 + 2 * halo;

    if (tid < 25) Wsm[tid] = Wt[c * 25 + tid];
    const float* ib = In + (long)bc * HW;
    for (int idx = tid; idx < tdim * tdim; idx += 256) {
        int r = idx / tdim, cc = idx - r * tdim;
        int hh = ty0 - halo + r, ww = tx0 - halo + cc;
        float v = 0.f;
        if ((unsigned)hh < 256u && (unsigned)ww < 256u)
            v = ib[hh * 256 + ww];
        Fs[r][cc] = v;
    }
    __syncthreads();

    float bv = Bias[c];
    float cav = fuse_gelu ? g_ca[bc] : 0.f;
#pragma unroll
    for (int i = 0; i < 4; i++) {
        int px = tid + i * 256;
        int ly = px >> 5, lx = px & 31;
        int h = ty0 + ly, w = tx0 + lx;
        float acc = bv;
#pragma unroll
        for (int kh = 0; kh < 5; kh++) {
            int hh = h + (kh - 2) * dil;
            if ((unsigned)hh >= 256u) continue;
#pragma unroll
            for (int kw = 0; kw < 5; kw++) {
                int ww = w + (kw - 2) * dil;
                if ((unsigned)ww >= 256u) continue;
                acc += Fs[ly + kh * dil][lx + kw * dil] * Wsm[kh * 5 + kw];
            }
        }
        long oidx = (long)bc * HW + h * 256 + w;
        if (!fuse_gelu) {
            Out[oidx] = acc;
        } else {
            float ge = 0.5f * acc * (1.f + erff(acc * 0.70710678118654752f));
            Out[oidx] = ge * cav + g_out[oidx];
        }
    }
}

// ---------------- launcher ----------------
extern "C" void kernel_launch(void* const* d_in, const int* in_sizes, int n_in,
                              void* d_out, int out_size)
{
    const float* x    = (const float*)d_in[0];
    const float* cg   = (const float*)d_in[1];
    const float* gu   = (const float*)d_in[2];
    const float* pv_w = (const float*)d_in[3];
    const float* pv_b = (const float*)d_in[4];
    const float* pq_w = (const float*)d_in[5];
    const float* pq_b = (const float*)d_in[6];
    const float* pk_w = (const float*)d_in[7];
    const float* pk_b = (const float*)d_in[8];
    const float* cs1_w = (const float*)d_in[9];
    const float* cs1_b = (const float*)d_in[10];
    const float* cs2_w = (const float*)d_in[11];
    const float* cs2_b = (const float*)d_in[12];
    const float* cs3_w = (const float*)d_in[13];
    const float* cs3_b = (const float*)d_in[14];
    const float* po_w  = (const float*)d_in[15];
    const float* po_b  = (const float*)d_in[16];
    const float* rin_w = (const float*)d_in[17];
    const float* rin_b = (const float*)d_in[18];
    const float* roff1_w = (const float*)d_in[19];
    const float* roff1_b = (const float*)d_in[20];
    const float* roff2_w = (const float*)d_in[21];
    const float* roff2_b = (const float*)d_in[22];
    const float* rm1_w = (const float*)d_in[23];
    const float* rm1_b = (const float*)d_in[24];
    const float* rm2_w = (const float*)d_in[25];
    const float* rm2_b = (const float*)d_in[26];
    const float* rca_w = (const float*)d_in[27];
    const float* rca_b = (const float*)d_in[28];
    const float* rsa_w = (const float*)d_in[29];
    const float* rsa_b = (const float*)d_in[30];
    float* out = (float*)d_out;

    float *p_cond, *p_f, *p_out, *p_b1, *p_b2;
    __nv_bfloat16 *p_whi, *p_wlo, *p_whi2, *p_wlo2, *p_whi3, *p_wlo3;
    __nv_bfloat16 *p_whi4, *p_wlo4, *p_whi5, *p_wlo5, *p_rwhi, *p_rwlo;
    cudaGetSymbolAddress((void**)&p_cond, g_cond);
    cudaGetSymbolAddress((void**)&p_f,    g_f);
    cudaGetSymbolAddress((void**)&p_out,  g_out);
    cudaGetSymbolAddress((void**)&p_b1,   g_b1);
    cudaGetSymbolAddress((void**)&p_b2,   g_b2);
    cudaGetSymbolAddress((void**)&p_whi,  g_whi);
    cudaGetSymbolAddress((void**)&p_wlo,  g_wlo);
    cudaGetSymbolAddress((void**)&p_whi2, g_whi2);
    cudaGetSymbolAddress((void**)&p_wlo2, g_wlo2);
    cudaGetSymbolAddress((void**)&p_whi3, g_whi3);
    cudaGetSymbolAddress((void**)&p_wlo3, g_wlo3);
    cudaGetSymbolAddress((void**)&p_whi4, g_whi4);
    cudaGetSymbolAddress((void**)&p_wlo4, g_wlo4);
    cudaGetSymbolAddress((void**)&p_whi5, g_whi5);
    cudaGetSymbolAddress((void**)&p_wlo5, g_wlo5);
    cudaGetSymbolAddress((void**)&p_rwhi, g_rwhi);
    cudaGetSymbolAddress((void**)&p_rwlo, g_rwlo);

    static int attr_set = 0;
    if (!attr_set) {
        cudaFuncSetAttribute(conv_mma, cudaFuncAttributeMaxDynamicSharedMemorySize,
                             CONV_SMEM);
        cudaFuncSetAttribute(rin_mma, cudaFuncAttributeMaxDynamicSharedMemorySize,
                             RIN_SMEM);
        cudaFuncSetAttribute(convqk_mma, cudaFuncAttributeMaxDynamicSharedMemorySize,
                             QK_SMEM);
        cudaFuncSetAttribute(attn_kernel, cudaFuncAttributeMaxDynamicSharedMemorySize,
                             AT_SMEM);
        attr_set = 1;
    }

    dim3 blk(256);
    int cgrid  = (BATCH * HW / 64) / TPB_CONV;   // 2048 (N=64 tiles)
    int qkgrid = (BATCH * HW / 128) / 2;         // 1024

    // 0. all weight pre-splits up front
    w_prep<<<64, blk>>>(pv_w, p_whi5, p_wlo5);
    w_prep<<<64, blk>>>(pq_w, p_whi,  p_wlo);
    w_prep<<<64, blk>>>(pk_w, p_whi2, p_wlo2);
    w_prep<<<64, blk>>>(cs1_w, p_whi3, p_wlo3);
    w_prep<<<64, blk>>>(po_w,  p_whi4, p_wlo4);
    w_prep_rin<<<16, blk>>>(rin_w, p_rwhi, p_rwlo);

    // 1. v = pv conv -> cond channels 0..127 (HMMA, 2 CTA/SM tiles)
    conv_mma<<<cgrid, blk, CONV_SMEM>>>(x, (long)CH * HW, p_whi5, p_wlo5, pv_b,
                                        p_cond, (long)CD * HW);
    // 2. f = leaky(rin conv)
    rin_mma<<<qkgrid, blk, RIN_SMEM>>>(p_cond, cg, rin_w, p_rwhi, p_rwlo,
                                       rin_b, p_f);
    // 3. offsets + predictor stats
    roff_kernel<<<BATCH * HW / 256, blk>>>(roff1_w, roff1_b, roff2_w, roff2_b);
    fmc_kernel<<<BATCH * HW / 256, blk>>>();
    fm_kernel<<<BATCH * C4, blk>>>();
    ca_kernel<<<1, BATCH * CH>>>(rca_w, rca_b);
    sa_kernel<<<BATCH * HW / 256, blk>>>(rsa_w, rsa_b);
    // 4. hard mask
    mask_kernel<<<BATCH * NWIN, blk>>>(rm1_w, rm1_b, rm2_w, rm2_b, gu);
    // 5. fused warp + q/k projections
    convqk_mma<<<qkgrid, blk, QK_SMEM>>>(x, p_whi, p_wlo, p_whi2, p_wlo2,
                                         pq_b, pk_b);
    // 6. fused attention
    attn_kernel<<<dim3(4, BATCH * NWIN), blk, AT_SMEM>>>();
    // 7. cs chain
    conv_mma<<<cgrid, blk, CONV_SMEM>>>(p_out, (long)CH * HW, p_whi3, p_wlo3, cs1_b,
                                        p_b1, (long)CH * HW);
    dw5_tiled<<<BATCH * CH * 64, blk>>>(p_b1, cs2_w, cs2_b, p_b2, 1, 0);
    dw5_tiled<<<BATCH * CH * 64, blk>>>(p_b2, cs3_w, cs3_b, p_b1, 3, 1);
    // 8. final projection
    conv_mma<<<cgrid, blk, CONV_SMEM>>>(p_b1, (long)CH * HW, p_whi4, p_wlo4, po_b,
                                        out, (long)CH * HW);
    (void)in_sizes; (void)n_in; (void)out_size;
}

// round 14
// speedup vs baseline: 1.0092x; 1.0092x over previous
#include <cuda_runtime.h>
#include <cuda_bf16.h>
#include <math.h>
#include <stdint.h>

// ---------------- constants ----------------
#define BATCH 4
#define CH    128
#define HW    65536          // 256*256
#define WS    16
#define NWIN  256            // windows per batch (16x16)
#define CD    131            // cond channels
#define C4    32
#define C8    16

// ---------------- scratch (device globals; no allocation) ----------------
__device__ float g_cond[(size_t)BATCH * CD * HW];
__device__ float g_f   [(size_t)BATCH * C4 * HW];
__device__ float g_fmc [(size_t)BATCH * HW];
__device__ float g_fm  [BATCH * C4];
__device__ float g_ca  [BATCH * CH];
__device__ float g_off [(size_t)BATCH * 2 * HW];
__device__ float g_sa  [(size_t)BATCH * HW];
__device__ float g_mask[BATCH * NWIN];
__device__ __nv_bfloat16 g_qwh[(size_t)BATCH * NWIN * 256 * CH];
__device__ __nv_bfloat16 g_qwl[(size_t)BATCH * NWIN * 256 * CH];
__device__ __nv_bfloat16 g_kwh[(size_t)BATCH * NWIN * 256 * CH];
__device__ __nv_bfloat16 g_kwl[(size_t)BATCH * NWIN * 256 * CH];
__device__ float g_out [(size_t)BATCH * CH * HW];
__device__ float g_b1  [(size_t)BATCH * CH * HW];
__device__ float g_b2  [(size_t)BATCH * CH * HW];
__device__ __nv_bfloat16 g_whi [CH * CH];   // pq
__device__ __nv_bfloat16 g_wlo [CH * CH];
__device__ __nv_bfloat16 g_whi2[CH * CH];   // pk
__device__ __nv_bfloat16 g_wlo2[CH * CH];
__device__ __nv_bfloat16 g_whi3[CH * CH];   // cs1
__device__ __nv_bfloat16 g_wlo3[CH * CH];
__device__ __nv_bfloat16 g_whi4[CH * CH];   // po
__device__ __nv_bfloat16 g_wlo4[CH * CH];
__device__ __nv_bfloat16 g_whi5[CH * CH];   // pv
__device__ __nv_bfloat16 g_wlo5[CH * CH];
__device__ __nv_bfloat16 g_rwhi[C4 * CH];
__device__ __nv_bfloat16 g_rwlo[C4 * CH];

// =====================================================================
// mma.sync helpers
// =====================================================================
__device__ __forceinline__ uint32_t smem_u32(const void* p) {
    uint32_t a;
    asm("{ .reg .u64 t; cvta.to.shared.u64 t, %1; cvt.u32.u64 %0, t; }"
        : "=r"(a) : "l"(p));
    return a;
}

__device__ __forceinline__ void ldsm4(uint32_t& r0, uint32_t& r1, uint32_t& r2, uint32_t& r3,
                                      uint32_t addr) {
    asm volatile("ldmatrix.sync.aligned.m8n8.x4.shared.b16 {%0,%1,%2,%3}, [%4];"
                 : "=r"(r0), "=r"(r1), "=r"(r2), "=r"(r3) : "r"(addr));
}
__device__ __forceinline__ void ldsm4t(uint32_t& r0, uint32_t& r1, uint32_t& r2, uint32_t& r3,
                                       uint32_t addr) {
    asm volatile("ldmatrix.sync.aligned.m8n8.x4.trans.shared.b16 {%0,%1,%2,%3}, [%4];"
                 : "=r"(r0), "=r"(r1), "=r"(r2), "=r"(r3) : "r"(addr));
}

__device__ __forceinline__ void mma_bf16(float* d, const uint32_t* a, uint32_t b0, uint32_t b1) {
    asm volatile("mma.sync.aligned.m16n8k16.row.col.f32.bf16.bf16.f32 "
                 "{%0,%1,%2,%3},{%4,%5,%6,%7},{%8,%9},{%0,%1,%2,%3};"
                 : "+f"(d[0]), "+f"(d[1]), "+f"(d[2]), "+f"(d[3])
                 : "r"(a[0]), "r"(a[1]), "r"(a[2]), "r"(a[3]), "r"(b0), "r"(b1));
}

// swizzled smem offset for [row][k] bf16, 128 k per row (256B rows)
__device__ __forceinline__ uint32_t swz(int row, int k) {
    return (uint32_t)(row * 256 + ((((k >> 3) ^ (row & 7))) << 4) + ((k & 7) << 1));
}
// 256 k per row (512B rows)
__device__ __forceinline__ uint32_t swzP(int row, int k) {
    return (uint32_t)(row * 512 + (((k >> 3) ^ (row & 7)) << 4) + ((k & 7) << 1));
}
// 64 k per row (128B rows)
__device__ __forceinline__ uint32_t swzV(int row, int k) {
    return (uint32_t)(row * 128 + ((((k >> 3) & 7) ^ (row & 7)) << 4) + ((k & 7) << 1));
}

__device__ __forceinline__ uint32_t pack2(float a, float b) {
    __nv_bfloat162 t = __floats2bfloat162_rn(a, b);
    return *(uint32_t*)&t;
}

// ---------------- W pre-split kernels ----------------
__global__ __launch_bounds__(256) void w_prep(const float* __restrict__ W,
                                              __nv_bfloat16* __restrict__ Whi,
                                              __nv_bfloat16* __restrict__ Wlo)
{
    int i = blockIdx.x * 256 + threadIdx.x;
    float x = W[i];
    __nv_bfloat16 h = __float2bfloat16(x);
    Whi[i] = h;
    Wlo[i] = __float2bfloat16(x - __bfloat162float(h));
}

__global__ __launch_bounds__(256) void w_prep_rin(const float* __restrict__ W,
                                                  __nv_bfloat16* __restrict__ Whi,
                                                  __nv_bfloat16* __restrict__ Wlo)
{
    int i = blockIdx.x * 256 + threadIdx.x;      // 4096 threads
    int co = i >> 7, k = i & 127;
    float x = W[co * 131 + k];
    __nv_bfloat16 h = __float2bfloat16(x);
    Whi[i] = h;
    Wlo[i] = __float2bfloat16(x - __bfloat162float(h));
}

// =====================================================================
// Tensor-core (HMMA) 1x1 conv (validated R6 kernel, N=128 tile)
// =====================================================================
#define WHI_OFF 0
#define WLO_OFF 32768
#define XHI_OFF 65536
#define XLO_OFF 98304
#define CONV_SMEM 131072
#define TPB_CONV 2

__global__ __launch_bounds__(256) void conv_mma(
    const float* __restrict__ In, long in_bstride,
    const __nv_bfloat16* __restrict__ Whi, const __nv_bfloat16* __restrict__ Wlo,
    const float* __restrict__ Bias,
    float* __restrict__ Out, long out_bstride)
{
    extern __shared__ char smc[];
    uint32_t sbase = smem_u32(smc);
    int tid = threadIdx.x, lane = tid & 31, wid = tid >> 5;
    int wm = wid & 3, wn = wid >> 2;
    int g = lane >> 2, q = lane & 3;

    for (int idx = tid; idx < 2048; idx += 256) {
        int co = idx >> 4, ch = idx & 15;
        uint32_t off = (uint32_t)co * 256u + (uint32_t)((ch ^ (co & 7)) << 4);
        *(uint4*)(smc + WHI_OFF + off) = ((const uint4*)Whi)[idx];
        *(uint4*)(smc + WLO_OFF + off) = ((const uint4*)Wlo)[idx];
    }

    for (int t = 0; t < TPB_CONV; t++) {
        int tile = blockIdx.x * TPB_CONV + t;
        int b = tile >> 9;
        int p0 = (tile & 511) << 7;
        const float* inb = In + (long)b * in_bstride + p0;

        __syncthreads();

#pragma unroll 4
        for (int it = 0; it < 16; it++) {
            int k = wid * 16 + it;
            float4 v = *(const float4*)(inb + (long)k * HW + lane * 4);
            __nv_bfloat16 h0 = __float2bfloat16(v.x), h1 = __float2bfloat16(v.y);
            __nv_bfloat16 h2 = __float2bfloat16(v.z), h3 = __float2bfloat16(v.w);
            uint2 hi, lo;
            hi.x = pack2(__bfloat162float(h0), __bfloat162float(h1));
            hi.y = pack2(__bfloat162float(h2), __bfloat162float(h3));
            lo.x = pack2(v.x - __bfloat162float(h0), v.y - __bfloat162float(h1));
            lo.y = pack2(v.z - __bfloat162float(h2), v.w - __bfloat162float(h3));
            uint32_t off = (uint32_t)k * 256u
                         + (uint32_t)((((lane >> 1) ^ (k & 7))) << 4)
                         + (uint32_t)((lane & 1) << 3);
            *(uint2*)(smc + XHI_OFF + off) = hi;
            *(uint2*)(smc + XLO_OFF + off) = lo;
        }
        __syncthreads();

        int jmat = lane >> 3, jrow = lane & 7;
        float acc[2][8][4] = {};
#pragma unroll
        for (int term = 0; term < 3; term++) {
            uint32_t a_base = sbase + (term == 2 ? WLO_OFF : WHI_OFF);
            uint32_t b_base = sbase + (term == 1 ? XLO_OFF : XHI_OFF);
#pragma unroll
            for (int k0 = 0; k0 < 128; k0 += 16) {
                int kk = k0 + ((lane >> 4) << 3);
                uint32_t a[2][4];
#pragma unroll
                for (int mf = 0; mf < 2; mf++)
                    ldsm4(a[mf][0], a[mf][1], a[mf][2], a[mf][3],
                          a_base + swz(wm * 32 + mf * 16 + (lane & 15), kk));
                uint32_t bf[4][4];
                int kr = k0 + ((jmat & 1) << 3) + jrow;
#pragma unroll
                for (int nb = 0; nb < 4; nb++) {
                    int nn = wn * 64 + nb * 16 + ((jmat >> 1) << 3);
                    uint32_t addr = b_base + (uint32_t)kr * 256u
                                  + (uint32_t)((((nn >> 3) ^ (kr & 7))) << 4);
                    ldsm4t(bf[nb][0], bf[nb][1], bf[nb][2], bf[nb][3], addr);
                }
#pragma unroll
                for (int mf = 0; mf < 2; mf++)
#pragma unroll
                    for (int nb = 0; nb < 4; nb++) {
                        mma_bf16(acc[mf][nb * 2 + 0], a[mf], bf[nb][0], bf[nb][1]);
                        mma_bf16(acc[mf][nb * 2 + 1], a[mf], bf[nb][2], bf[nb][3]);
                    }
            }
        }

        float* ob = Out + (long)b * out_bstride;
#pragma unroll
        for (int mf = 0; mf < 2; mf++) {
            int co0 = wm * 32 + mf * 16 + g;
            float bv0 = Bias[co0], bv1 = Bias[co0 + 8];
            float* r0 = ob + (long)co0 * HW + p0;
            float* r1 = ob + (long)(co0 + 8) * HW + p0;
#pragma unroll
            for (int nf = 0; nf < 8; nf++) {
                int col = wn * 64 + nf * 8 + q * 2;
                float2 v0 = {acc[mf][nf][0] + bv0, acc[mf][nf][1] + bv0};
                float2 v1 = {acc[mf][nf][2] + bv1, acc[mf][nf][3] + bv1};
                *(float2*)(r0 + col) = v0;
                *(float2*)(r1 + col) = v1;
            }
        }
    }
}

// =====================================================================
// rin HMMA conv (validated R8 kernel)
// =====================================================================
#define RW_HI 0
#define RW_LO 8192
#define RX_HI 16384
#define RX_LO 49152
#define RIN_SMEM 81920

__global__ __launch_bounds__(256) void rin_mma(
    const float* __restrict__ cond,
    const float* __restrict__ cg,
    const float* __restrict__ rw,
    const __nv_bfloat16* __restrict__ Whi, const __nv_bfloat16* __restrict__ Wlo,
    const float* __restrict__ Bias,
    float* __restrict__ Out)
{
    extern __shared__ char smc[];
    uint32_t sbase = smem_u32(smc);
    int tid = threadIdx.x, lane = tid & 31, wid = tid >> 5;
    int wm = wid & 1, wn = wid >> 1;
    int g = lane >> 2, q = lane & 3;

    for (int idx = tid; idx < 512; idx += 256) {
        int co = idx >> 4, ch = idx & 15;
        uint32_t off = (uint32_t)co * 256u + (uint32_t)((ch ^ (co & 7)) << 4);
        *(uint4*)(smc + RW_HI + off) = ((const uint4*)Whi)[idx];
        *(uint4*)(smc + RW_LO + off) = ((const uint4*)Wlo)[idx];
    }

    for (int t = 0; t < TPB_CONV; t++) {
        int tile = blockIdx.x * TPB_CONV + t;
        int b = tile >> 9;
        int p0 = (tile & 511) << 7;
        const float* inb = cond + (long)b * CD * HW + p0;

        __syncthreads();

#pragma unroll 4
        for (int it = 0; it < 16; it++) {
            int k = wid * 16 + it;
            float4 v = *(const float4*)(inb + (long)k * HW + lane * 4);
            __nv_bfloat16 h0 = __float2bfloat16(v.x), h1 = __float2bfloat16(v.y);
            __nv_bfloat16 h2 = __float2bfloat16(v.z), h3 = __float2bfloat16(v.w);
            uint2 hi, lo;
            hi.x = pack2(__bfloat162float(h0), __bfloat162float(h1));
            hi.y = pack2(__bfloat162float(h2), __bfloat162float(h3));
            lo.x = pack2(v.x - __bfloat162float(h0), v.y - __bfloat162float(h1));
            lo.y = pack2(v.z - __bfloat162float(h2), v.w - __bfloat162float(h3));
            uint32_t off = (uint32_t)k * 256u
                         + (uint32_t)((((lane >> 1) ^ (k & 7))) << 4)
                         + (uint32_t)((lane & 1) << 3);
            *(uint2*)(smc + RX_HI + off) = hi;
            *(uint2*)(smc + RX_LO + off) = lo;
        }
        __syncthreads();

        int jmat = lane >> 3, jrow = lane & 7;
        float acc[4][4] = {};
#pragma unroll
        for (int term = 0; term < 3; term++) {
            uint32_t a_base = sbase + (term == 2 ? RW_LO : RW_HI);
            uint32_t b_base = sbase + (term == 1 ? RX_LO : RX_HI);
#pragma unroll
            for (int k0 = 0; k0 < 128; k0 += 16) {
                int kk = k0 + ((lane >> 4) << 3);
                uint32_t a[4];
                ldsm4(a[0], a[1], a[2], a[3],
                      a_base + swz(wm * 16 + (lane & 15), kk));
                int kr = k0 + ((jmat & 1) << 3) + jrow;
#pragma unroll
                for (int nb = 0; nb < 2; nb++) {
                    int nn = wn * 32 + nb * 16 + ((jmat >> 1) << 3);
                    uint32_t addr = b_base + (uint32_t)kr * 256u
                                  + (uint32_t)((((nn >> 3) ^ (kr & 7))) << 4);
                    uint32_t bf[4];
                    ldsm4t(bf[0], bf[1], bf[2], bf[3], addr);
                    mma_bf16(acc[nb * 2 + 0], a, bf[0], bf[1]);
                    mma_bf16(acc[nb * 2 + 1], a, bf[2], bf[3]);
                }
            }
        }

        int co0 = wm * 16 + g;
        int co1 = co0 + 8;
        float bv0 = Bias[co0], bv1 = Bias[co1];
        float wa0 = rw[co0 * 131 + 128], wa1 = rw[co0 * 131 + 129], wa2 = rw[co0 * 131 + 130];
        float wb0 = rw[co1 * 131 + 128], wb1 = rw[co1 * 131 + 129], wb2 = rw[co1 * 131 + 130];
        const float* cgb = cg + (long)b * HW;
        float* ob = Out + (long)b * C4 * HW;
#pragma unroll
        for (int nf = 0; nf < 4; nf++) {
#pragma unroll
            for (int e = 0; e < 2; e++) {
                int px = wn * 32 + nf * 8 + q * 2 + e;
                int p = p0 + px;
                int hh = p >> 8, ww = p & 255;
                float ly = -1.f + (2.f / 15.f) * (float)(hh & 15);
                float lx = -1.f + (2.f / 15.f) * (float)(ww & 15);
                float cgv = cgb[p];
                float v0 = acc[nf][e]     + bv0 + wa0 * cgv + wa1 * ly + wa2 * lx;
                float v1 = acc[nf][e + 2] + bv1 + wb0 * cgv + wb1 * ly + wb2 * lx;
                v0 = v0 > 0.f ? v0 : 0.2f * v0;
                v1 = v1 > 0.f ? v1 : 0.2f * v1;
                ob[(long)co0 * HW + p] = v0;
                ob[(long)co1 * HW + p] = v1;
            }
        }
    }
}

// =====================================================================
// Fused warp + q-proj + k-proj; emits packed bf16 hi/lo Q/K directly
// (same conversion of the same fp32 values attn used to perform).
// =====================================================================
#define QW_HI 0
#define QW_LO 32768
#define KW_HI 65536
#define KW_LO 98304
#define QX_HI 131072
#define QX_LO 163840
#define QSTG  131072
#define QPRM  196608
#define QK_SMEM 200704

__global__ __launch_bounds__(256) void convqk_mma(
    const float* __restrict__ x,
    const __nv_bfloat16* __restrict__ Wqhi, const __nv_bfloat16* __restrict__ Wqlo,
    const __nv_bfloat16* __restrict__ Wkhi, const __nv_bfloat16* __restrict__ Wklo,
    const float* __restrict__ Bq, const float* __restrict__ Bk)
{
    extern __shared__ char smc[];
    uint32_t sbase = smem_u32(smc);
    int tid = threadIdx.x, lane = tid & 31, wid = tid >> 5;
    int wm = wid & 3, wn = wid >> 2;
    int g = lane >> 2, q = lane & 3;

    int*   i00s = (int*)(smc + QPRM);
    int*   i01s = i00s + 128;
    int*   i10s = i00s + 256;
    int*   i11s = i00s + 384;
    float* w00s = (float*)(i00s + 512);
    float* w01s = w00s + 128;
    float* w10s = w00s + 256;
    float* w11s = w00s + 384;

    for (int idx = tid; idx < 2048; idx += 256) {
        int co = idx >> 4, ch = idx & 15;
        uint32_t off = (uint32_t)co * 256u + (uint32_t)((ch ^ (co & 7)) << 4);
        *(uint4*)(smc + QW_HI + off) = ((const uint4*)Wqhi)[idx];
        *(uint4*)(smc + QW_LO + off) = ((const uint4*)Wqlo)[idx];
        *(uint4*)(smc + KW_HI + off) = ((const uint4*)Wkhi)[idx];
        *(uint4*)(smc + KW_LO + off) = ((const uint4*)Wklo)[idx];
    }

    for (int t = 0; t < 2; t++) {
        int tile = blockIdx.x * 2 + t;
        int b = tile >> 9;
        int p0 = (tile & 511) << 7;

        __syncthreads();

        if (tid < 128) {
            int p = p0 + tid;
            int h = p >> 8, w = p & 255;
            float fx = g_off[(long)b * 2 * HW + p];
            float fy = g_off[(long)b * 2 * HW + HW + p];
            float sx = fminf(fmaxf((float)w + fx, 0.f), 255.f);
            float sy = fminf(fmaxf((float)h + fy, 0.f), 255.f);
            float x0f = floorf(sx), y0f = floorf(sy);
            float x1f = fminf(x0f + 1.f, 255.f), y1f = fminf(y0f + 1.f, 255.f);
            float wx = sx - x0f, wy = sy - y0f;
            int x0 = (int)x0f, x1 = (int)x1f, y0 = (int)y0f, y1 = (int)y1f;
            i00s[tid] = y0 * 256 + x0; i01s[tid] = y0 * 256 + x1;
            i10s[tid] = y1 * 256 + x0; i11s[tid] = y1 * 256 + x1;
            w00s[tid] = (1.f - wx) * (1.f - wy); w01s[tid] = wx * (1.f - wy);
            w10s[tid] = (1.f - wx) * wy;         w11s[tid] = wx * wy;
        }
        __syncthreads();

        {
            int4  I00 = ((const int4*)i00s)[lane], I01 = ((const int4*)i01s)[lane];
            int4  I10 = ((const int4*)i10s)[lane], I11 = ((const int4*)i11s)[lane];
            float4 W00 = ((const float4*)w00s)[lane], W01 = ((const float4*)w01s)[lane];
            float4 W10 = ((const float4*)w10s)[lane], W11 = ((const float4*)w11s)[lane];
            const float* xb = x + (long)b * CH * HW;
#pragma unroll 4
            for (int it = 0; it < 16; it++) {
                int k = wid * 16 + it;
                const float* xc = xb + (long)k * HW;
                float vv[4];
                vv[0] = W00.x * xc[I00.x] + W01.x * xc[I01.x] + W10.x * xc[I10.x] + W11.x * xc[I11.x];
                vv[1] = W00.y * xc[I00.y] + W01.y * xc[I01.y] + W10.y * xc[I10.y] + W11.y * xc[I11.y];
                vv[2] = W00.z * xc[I00.z] + W01.z * xc[I01.z] + W10.z * xc[I10.z] + W11.z * xc[I11.z];
                vv[3] = W00.w * xc[I00.w] + W01.w * xc[I01.w] + W10.w * xc[I10.w] + W11.w * xc[I11.w];
                __nv_bfloat16 h0 = __float2bfloat16(vv[0]), h1 = __float2bfloat16(vv[1]);
                __nv_bfloat16 h2 = __float2bfloat16(vv[2]), h3 = __float2bfloat16(vv[3]);
                uint2 hi, lo;
                hi.x = pack2(__bfloat162float(h0), __bfloat162float(h1));
                hi.y = pack2(__bfloat162float(h2), __bfloat162float(h3));
                lo.x = pack2(vv[0] - __bfloat162float(h0), vv[1] - __bfloat162float(h1));
                lo.y = pack2(vv[2] - __bfloat162float(h2), vv[3] - __bfloat162float(h3));
                uint32_t off = (uint32_t)k * 256u
                             + (uint32_t)((((lane >> 1) ^ (k & 7))) << 4)
                             + (uint32_t)((lane & 1) << 3);
                *(uint2*)(smc + QX_HI + off) = hi;
                *(uint2*)(smc + QX_LO + off) = lo;
            }
        }
        __syncthreads();

        int jmat = lane >> 3, jrow = lane & 7;
        float accq[2][8][4] = {};
        float acck[2][8][4] = {};
#pragma unroll
        for (int term = 0; term < 3; term++) {
            uint32_t aq_base = sbase + (term == 2 ? QW_LO : QW_HI);
            uint32_t ak_base = sbase + (term == 2 ? KW_LO : KW_HI);
            uint32_t b_base  = sbase + (term == 1 ? QX_LO : QX_HI);
#pragma unroll
            for (int k0 = 0; k0 < 128; k0 += 16) {
                int kk = k0 + ((lane >> 4) << 3);
                uint32_t aq[2][4], ak[2][4];
#pragma unroll
                for (int mf = 0; mf < 2; mf++) {
                    ldsm4(aq[mf][0], aq[mf][1], aq[mf][2], aq[mf][3],
                          aq_base + swz(wm * 32 + mf * 16 + (lane & 15), kk));
                    ldsm4(ak[mf][0], ak[mf][1], ak[mf][2], ak[mf][3],
                          ak_base + swz(wm * 32 + mf * 16 + (lane & 15), kk));
                }
                int kr = k0 + ((jmat & 1) << 3) + jrow;
#pragma unroll
                for (int nb = 0; nb < 4; nb++) {
                    int nn = wn * 64 + nb * 16 + ((jmat >> 1) << 3);
                    uint32_t addr = b_base + (uint32_t)kr * 256u
                                  + (uint32_t)((((nn >> 3) ^ (kr & 7))) << 4);
                    uint32_t bf[4];
                    ldsm4t(bf[0], bf[1], bf[2], bf[3], addr);
#pragma unroll
                    for (int mf = 0; mf < 2; mf++) {
                        mma_bf16(accq[mf][nb * 2 + 0], aq[mf], bf[0], bf[1]);
                        mma_bf16(accq[mf][nb * 2 + 1], aq[mf], bf[2], bf[3]);
                        mma_bf16(acck[mf][nb * 2 + 0], ak[mf], bf[0], bf[1]);
                        mma_bf16(acck[mf][nb * 2 + 1], ak[mf], bf[2], bf[3]);
                    }
                }
            }
        }

        float* St = (float*)(smc + QSTG);
        // ---- stage + convert + write q ----
        __syncthreads();
#pragma unroll
        for (int mf = 0; mf < 2; mf++) {
            int co0 = wm * 32 + mf * 16 + g;
            uint32_t perm = (uint32_t)(q << 3);
#pragma unroll
            for (int nf = 0; nf < 8; nf++) {
                int px = wn * 64 + nf * 8 + q * 2;
                St[px * 128 + (co0 ^ perm)]             = accq[mf][nf][0];
                St[(px + 1) * 128 + (co0 ^ perm)]       = accq[mf][nf][1];
                St[px * 128 + ((co0 + 8) ^ perm)]       = accq[mf][nf][2];
                St[(px + 1) * 128 + ((co0 + 8) ^ perm)] = accq[mf][nf][3];
            }
        }
        __syncthreads();
#pragma unroll
        for (int it = 0; it < 16; it++) {
            int idx = it * 256 + tid;
            int px = idx >> 5, cc = (idx & 31) * 4;
            uint32_t perm = (uint32_t)(((px >> 1) & 3) << 3);
            float4 vv = *(float4*)(St + px * 128 + (cc ^ perm));
            float4 bb = *(const float4*)(Bq + cc);
            vv.x += bb.x; vv.y += bb.y; vv.z += bb.z; vv.w += bb.w;
            __nv_bfloat16 h0 = __float2bfloat16(vv.x), h1 = __float2bfloat16(vv.y);
            __nv_bfloat16 h2 = __float2bfloat16(vv.z), h3 = __float2bfloat16(vv.w);
            uint2 hi, lo;
            hi.x = pack2(__bfloat162float(h0), __bfloat162float(h1));
            hi.y = pack2(__bfloat162float(h2), __bfloat162float(h3));
            lo.x = pack2(vv.x - __bfloat162float(h0), vv.y - __bfloat162float(h1));
            lo.y = pack2(vv.z - __bfloat162float(h2), vv.w - __bfloat162float(h3));
            int p = p0 + px;
            int h = p >> 8, w = p & 255;
            long a0 = ((long)(b * NWIN + (h >> 4) * 16 + (w >> 4)) * 256
                       + (h & 15) * 16 + (w & 15)) * CH + cc;
            *(uint2*)(g_qwh + a0) = hi;
            *(uint2*)(g_qwl + a0) = lo;
        }
        // ---- stage + convert + write k ----
        __syncthreads();
#pragma unroll
        for (int mf = 0; mf < 2; mf++) {
            int co0 = wm * 32 + mf * 16 + g;
            uint32_t perm = (uint32_t)(q << 3);
#pragma unroll
            for (int nf = 0; nf < 8; nf++) {
                int px = wn * 64 + nf * 8 + q * 2;
                St[px * 128 + (co0 ^ perm)]             = acck[mf][nf][0];
                St[(px + 1) * 128 + (co0 ^ perm)]       = acck[mf][nf][1];
                St[px * 128 + ((co0 + 8) ^ perm)]       = acck[mf][nf][2];
                St[(px + 1) * 128 + ((co0 + 8) ^ perm)] = acck[mf][nf][3];
            }
        }
        __syncthreads();
#pragma unroll
        for (int it = 0; it < 16; it++) {
            int idx = it * 256 + tid;
            int px = idx >> 5, cc = (idx & 31) * 4;
            uint32_t perm = (uint32_t)(((px >> 1) & 3) << 3);
            float4 vv = *(float4*)(St + px * 128 + (cc ^ perm));
            float4 bb = *(const float4*)(Bk + cc);
            vv.x += bb.x; vv.y += bb.y; vv.z += bb.z; vv.w += bb.w;
            __nv_bfloat16 h0 = __float2bfloat16(vv.x), h1 = __float2bfloat16(vv.y);
            __nv_bfloat16 h2 = __float2bfloat16(vv.z), h3 = __float2bfloat16(vv.w);
            uint2 hi, lo;
            hi.x = pack2(__bfloat162float(h0), __bfloat162float(h1));
            hi.y = pack2(__bfloat162float(h2), __bfloat162float(h3));
            lo.x = pack2(vv.x - __bfloat162float(h0), vv.y - __bfloat162float(h1));
            lo.y = pack2(vv.z - __bfloat162float(h2), vv.w - __bfloat162float(h3));
            int p = p0 + px;
            int h = p >> 8, w = p & 255;
            long a0 = ((long)(b * NWIN + (h >> 4) * 16 + (w >> 4)) * 256
                       + (h & 15) * 16 + (w & 15)) * CH + cc;
            *(uint2*)(g_kwh + a0) = hi;
            *(uint2*)(g_kwl + a0) = lo;
        }
    }
}

// =====================================================================
// Fused window attention: Q/K now pre-packed bf16 hi/lo -> pure copies.
// =====================================================================
#define AT_QHI 0
#define AT_QLO 16384
#define AT_KHI 32768
#define AT_KLO 49152
#define AT_PHI 0
#define AT_PLO 32768
#define AT_S   65536
#define AT_SROW 260
#define AT_S2  65536
#define AT_VHI 132096
#define AT_VLO 148480
#define AT_SMEM 164864

__global__ __launch_bounds__(256) void attn_kernel()
{
    int win = blockIdx.y;
    int i0 = blockIdx.x * 64;
    int b = win >> 8, n = win & 255;
    int wy = n >> 4, wx = n & 15;
    const float* vbase = g_cond + (long)b * CD * HW;
    int tid = threadIdx.x, lane = tid & 31, wid = tid >> 5;

    if (g_mask[win] == 0.f) {
        const float* sab = g_sa + (long)b * HW;
        float* ob = g_out + (long)b * CH * HW;
#pragma unroll 4
        for (int it = 0; it < 32; it++) {
            int idx = it * 256 + tid;
            int c = idx >> 6, pxl = idx & 63;
            int i = i0 + pxl;
            int p = (wy * 16 + (i >> 4)) * 256 + wx * 16 + (i & 15);
            ob[(long)c * HW + p] = vbase[(long)c * HW + p] * sab[p];
        }
        return;
    }

    extern __shared__ char smc[];
    uint32_t sbase = smem_u32(smc);
    int wm = wid & 3, wn = wid >> 2;
    int g = lane >> 2, q = lane & 3;

    // ---- load Q tile: packed bf16 hi/lo copy ----
    {
        const __nv_bfloat16* Qh = g_qwh + ((long)win * 256 + i0) * CH;
        const __nv_bfloat16* Ql = g_qwl + ((long)win * 256 + i0) * CH;
#pragma unroll
        for (int it = 0; it < 8; it++) {
            int e = it * 256 + tid;
            int row = e >> 5, k = (e & 31) * 4;
            uint2 hi = *(const uint2*)(Qh + row * CH + k);
            uint2 lo = *(const uint2*)(Ql + row * CH + k);
            uint32_t off = swz(row, k);
            *(uint2*)(smc + AT_QHI + off) = hi;
            *(uint2*)(smc + AT_QLO + off) = lo;
        }
    }

    float* Ssm = (float*)(smc + AT_S);
    for (int kc = 0; kc < 4; kc++) {
        __syncthreads();
        const __nv_bfloat16* Kh = g_kwh + ((long)win * 256 + kc * 64) * CH;
        const __nv_bfloat16* Kl = g_kwl + ((long)win * 256 + kc * 64) * CH;
#pragma unroll
        for (int it = 0; it < 8; it++) {
            int e = it * 256 + tid;
            int row = e >> 5, k = (e & 31) * 4;
            uint2 hi = *(const uint2*)(Kh + row * CH + k);
            uint2 lo = *(const uint2*)(Kl + row * CH + k);
            uint32_t off = swz(row, k);
            *(uint2*)(smc + AT_KHI + off) = hi;
            *(uint2*)(smc + AT_KLO + off) = lo;
        }
        __syncthreads();

        float acc[4][4] = {};
#pragma unroll
        for (int term = 0; term < 3; term++) {
            uint32_t a_base = sbase + (term == 2 ? AT_QLO : AT_QHI);
            uint32_t b_base = sbase + (term == 1 ? AT_KLO : AT_KHI);
#pragma unroll
            for (int k0 = 0; k0 < 128; k0 += 16) {
                int kk = k0 + ((lane >> 4) << 3);
                uint32_t a[4];
                ldsm4(a[0], a[1], a[2], a[3],
                      a_base + swz(wm * 16 + (lane & 15), kk));
#pragma unroll
                for (int nb = 0; nb < 2; nb++) {
                    uint32_t bf[4];
                    ldsm4(bf[0], bf[1], bf[2], bf[3],
                          b_base + swz(wn * 32 + nb * 16 + (lane & 15), kk));
                    mma_bf16(acc[nb * 2 + 0], a, bf[0], bf[2]);
                    mma_bf16(acc[nb * 2 + 1], a, bf[1], bf[3]);
                }
            }
        }
        int srow = wm * 16 + g;
        int scol0 = kc * 64 + wn * 32;
#pragma unroll
        for (int nf = 0; nf < 4; nf++) {
            int col = scol0 + nf * 8 + q * 2;
            Ssm[srow * AT_SROW + col]           = acc[nf][0];
            Ssm[srow * AT_SROW + col + 1]       = acc[nf][1];
            Ssm[(srow + 8) * AT_SROW + col]     = acc[nf][2];
            Ssm[(srow + 8) * AT_SROW + col + 1] = acc[nf][3];
        }
    }
    __syncthreads();

    for (int r = wid; r < 64; r += 8) {
        float v[8];
        float mx = -1e30f;
#pragma unroll
        for (int kk = 0; kk < 8; kk++) { v[kk] = Ssm[r * AT_SROW + lane + 32 * kk]; mx = fmaxf(mx, v[kk]); }
#pragma unroll
        for (int o = 16; o > 0; o >>= 1) mx = fmaxf(mx, __shfl_xor_sync(0xffffffffu, mx, o));
        float s = 0.f;
#pragma unroll
        for (int kk = 0; kk < 8; kk++) { v[kk] = expf(v[kk] - mx); s += v[kk]; }
#pragma unroll
        for (int o = 16; o > 0; o >>= 1) s += __shfl_xor_sync(0xffffffffu, s, o);
        float inv = 1.f / s;
#pragma unroll
        for (int kk = 0; kk < 8; kk++) {
            float pv = v[kk] * inv;
            __nv_bfloat16 h = __float2bfloat16(pv);
            __nv_bfloat16 l = __float2bfloat16(pv - __bfloat162float(h));
            uint32_t off = swzP(r, lane + 32 * kk);
            *(__nv_bfloat16*)(smc + AT_PHI + off) = h;
            *(__nv_bfloat16*)(smc + AT_PLO + off) = l;
        }
    }

    float oacc[8][4] = {};
    for (int kc = 0; kc < 4; kc++) {
        __syncthreads();
#pragma unroll 4
        for (int it = 0; it < 32; it++) {
            int idx = it * 256 + tid;
            int c = idx >> 6, jl = idx & 63;
            int j = kc * 64 + jl;
            int p = (wy * 16 + (j >> 4)) * 256 + wx * 16 + (j & 15);
            float xv = vbase[(long)c * HW + p];
            __nv_bfloat16 h = __float2bfloat16(xv);
            __nv_bfloat16 l = __float2bfloat16(xv - __bfloat162float(h));
            uint32_t off = swzV(c, jl);
            *(__nv_bfloat16*)(smc + AT_VHI + off) = h;
            *(__nv_bfloat16*)(smc + AT_VLO + off) = l;
        }
        __syncthreads();
#pragma unroll
        for (int term = 0; term < 3; term++) {
            uint32_t a_base = sbase + (term == 2 ? AT_PLO : AT_PHI);
            uint32_t b_base = sbase + (term == 1 ? AT_VLO : AT_VHI);
#pragma unroll
            for (int ks = 0; ks < 64; ks += 16) {
                int kk = ks + ((lane >> 4) << 3);
                uint32_t a[4];
                ldsm4(a[0], a[1], a[2], a[3],
                      a_base + swzP(wm * 16 + (lane & 15), kc * 64 + kk));
#pragma unroll
                for (int nb = 0; nb < 4; nb++) {
                    uint32_t bf[4];
                    ldsm4(bf[0], bf[1], bf[2], bf[3],
                          b_base + swzV(wn * 64 + nb * 16 + (lane & 15), kk));
                    mma_bf16(oacc[nb * 2 + 0], a, bf[0], bf[2]);
                    mma_bf16(oacc[nb * 2 + 1], a, bf[1], bf[3]);
                }
            }
        }
    }

    __syncthreads();
    float* S2 = (float*)(smc + AT_S2);
    {
        int prow = wm * 16 + g;
#pragma unroll
        for (int nf = 0; nf < 8; nf++) {
            int ch = wn * 64 + nf * 8 + q * 2;
            S2[ch * 68 + prow]           = oacc[nf][0];
            S2[(ch + 1) * 68 + prow]     = oacc[nf][1];
            S2[ch * 68 + prow + 8]       = oacc[nf][2];
            S2[(ch + 1) * 68 + prow + 8] = oacc[nf][3];
        }
    }
    __syncthreads();
    {
        float* ob = g_out + (long)b * CH * HW;
#pragma unroll 4
        for (int it = 0; it < 32; it++) {
            int idx = it * 256 + tid;
            int c = idx >> 6, pxl = idx & 63;
            int i = i0 + pxl;
            int p = (wy * 16 + (i >> 4)) * 256 + wx * 16 + (i & 15);
            ob[(long)c * HW + p] = S2[c * 68 + pxl];
        }
    }
}

// ---------------- offsets head + fused channel-mean (identical order) ----------------
__global__ __launch_bounds__(256) void roff_kernel(
    const float* __restrict__ w1, const float* __restrict__ b1,
    const float* __restrict__ w2, const float* __restrict__ b2)
{
    __shared__ float W1[16 * 32], B1[16], W2[2 * 16], B2[2];
    int t = threadIdx.x;
    for (int i = t; i < 512; i += 256) W1[i] = w1[i];
    if (t < 16) B1[t] = b1[t];
    if (t < 32) W2[t] = w2[t];
    if (t < 2)  B2[t] = b2[t];
    __syncthreads();
    int idx = blockIdx.x * 256 + t;
    int b = idx >> 16, p = idx & 65535;
    float fv[32];
    const float* fb = g_f + (long)b * C4 * HW + p;
#pragma unroll
    for (int c = 0; c < 32; c++) fv[c] = fb[(long)c * HW];

    // fused fmc: same summation order as the old fmc_kernel
    float s = 0.f;
#pragma unroll
    for (int c = 0; c < 32; c++) s += fv[c];
    g_fmc[idx] = s * (1.f / 32.f);

    float o0 = B2[0], o1 = B2[1];
#pragma unroll
    for (int o = 0; o < 16; o++) {
        float h = B1[o];
#pragma unroll
        for (int c = 0; c < 32; c++) h += W1[o * 32 + c] * fv[c];
        h = h > 0.f ? h : 0.2f * h;
        o0 += W2[o] * h;
        o1 += W2[16 + o] * h;
    }
    g_off[(long)b * 2 * HW + p]      = o0;
    g_off[(long)b * 2 * HW + HW + p] = o1;
}

// ---------------- spatial mean of f ----------------
__global__ __launch_bounds__(256) void fm_kernel()
{
    int bc = blockIdx.x;
    const float* src = g_f + (long)bc * HW;
    float s = 0.f;
    for (int i = threadIdx.x; i < HW; i += 256) s += src[i];
    __shared__ float red[256];
    red[threadIdx.x] = s; __syncthreads();
    for (int st = 128; st > 0; st >>= 1) {
        if (threadIdx.x < st) red[threadIdx.x] += red[threadIdx.x + st];
        __syncthreads();
    }
    if (threadIdx.x == 0) g_fm[bc] = red[0] * (1.f / 65536.f);
}

__global__ void ca_kernel(const float* __restrict__ w, const float* __restrict__ bias)
{
    int t = threadIdx.x;
    int b = t >> 7, co = t & 127;
    float a = bias[co];
#pragma unroll
    for (int k = 0; k < 32; k++) a += w[co * 32 + k] * g_fm[b * 32 + k];
    g_ca[t] = 1.f / (1.f + expf(-a));
}

// ---------------- spatial attention ----------------
__global__ __launch_bounds__(256) void sa_kernel(const float* __restrict__ w, const float* __restrict__ bias)
{
    __shared__ float Wsm[32 * 9];
    for (int i = threadIdx.x; i < 288; i += 256) Wsm[i] = w[i];
    __syncthreads();
    int idx = blockIdx.x * 256 + threadIdx.x;
    int b = idx >> 16, p = idx & 65535;
    int h = p >> 8, wc = p & 255;
    float acc = bias[0];
    const float* fb = g_f + (long)b * C4 * HW;
    for (int c = 0; c < 32; c++) {
        const float* fc = fb + (long)c * HW;
#pragma unroll
        for (int kh = 0; kh < 3; kh++) {
            int hh = h + kh - 1;
            if ((unsigned)hh >= 256u) continue;
#pragma unroll
            for (int kw = 0; kw < 3; kw++) {
                int ww = wc + kw - 1;
                if ((unsigned)ww >= 256u) continue;
                acc += fc[hh * 256 + ww] * Wsm[c * 9 + kh * 3 + kw];
            }
        }
    }
    g_sa[idx] = 1.f / (1.f + expf(-acc));
}

// ---------------- window mask ----------------
__global__ __launch_bounds__(256) void mask_kernel(
    const float* __restrict__ rm1w, const float* __restrict__ rm1b,
    const float* __restrict__ rm2w, const float* __restrict__ rm2b,
    const float* __restrict__ gu)
{
    __shared__ float mw[256];
    __shared__ float hs[16];
    int win = blockIdx.x;
    int b = win >> 8, n = win & 255;
    int wy = n >> 4, wx = n & 15;
    int e = threadIdx.x;
    int dh = e >> 4, dw = e & 15;
    int p = (wy * 16 + dh) * 256 + wx * 16 + dw;
    mw[e] = g_fmc[(long)b * HW + p];
    __syncthreads();
    if (e < 16) {
        float h = rm1b[e];
        for (int k = 0; k < 256; k++) h += rm1w[e * 256 + k] * mw[k];
        hs[e] = h > 0.f ? h : 0.2f * h;
    }
    __syncthreads();
    if (e == 0) {
        float l0 = rm2b[0], l1 = rm2b[1];
#pragma unroll
        for (int k = 0; k < 16; k++) { l0 += rm2w[k] * hs[k]; l1 += rm2w[16 + k] * hs[k]; }
        float m = fmaxf(l0, l1);
        float p0 = expf(l0 - m), p1 = expf(l1 - m);
        float s = p0 + p1; p0 /= s; p1 /= s;
        float u0 = gu[(long)win * 2 + 0], u1 = gu[(long)win * 2 + 1];
        float q0 = -logf(-logf(u0 + 1e-10f) + 1e-10f);
        float q1 = -logf(-logf(u1 + 1e-10f) + 1e-10f);
        g_mask[win] = (p0 + q0 >= p1 + q1) ? 1.f : 0.f;
    }
}

// =====================================================================
// Smem-tiled depthwise 5x5 (validated R10 kernel)
// =====================================================================
__global__ __launch_bounds__(256) void dw5_tiled(
    const float* __restrict__ In, const float* __restrict__ Wt,
    const float* __restrict__ Bias, float* __restrict__ Out,
    int dil, int fuse_gelu)
{
    __shared__ float Fs[44][44];
    __shared__ float Wsm[25];
    int blk = blockIdx.x;
    int tile = blk & 63;
    int bc = blk >> 6;
    int c = bc & 127;
    int ty0 = (tile >> 3) * 32, tx0 = (tile & 7) * 32;
    int tid = threadIdx.x;
    int halo = 2 * dil;
    int tdim = 32 + 2 * halo;

    if (tid < 25) Wsm[tid] = Wt[c * 25 + tid];
    const float* ib = In + (long)bc * HW;
    for (int idx = tid; idx < tdim * tdim; idx += 256) {
        int r = idx / tdim, cc = idx - r * tdim;
        int hh = ty0 - halo + r, ww = tx0 - halo + cc;
        float v = 0.f;
        if ((unsigned)hh < 256u && (unsigned)ww < 256u)
            v = ib[hh * 256 + ww];
        Fs[r][cc] = v;
    }
    __syncthreads();

    float bv = Bias[c];
    float cav = fuse_gelu ? g_ca[bc] : 0.f;
#pragma unroll
    for (int i = 0; i < 4; i++) {
        int px = tid + i * 256;
        int ly = px >> 5, lx = px & 31;
        int h = ty0 + ly, w = tx0 + lx;
        float acc = bv;
#pragma unroll
        for (int kh = 0; kh < 5; kh++) {
            int hh = h + (kh - 2) * dil;
            if ((unsigned)hh >= 256u) continue;
#pragma unroll
            for (int kw = 0; kw < 5; kw++) {
                int ww = w + (kw - 2) * dil;
                if ((unsigned)ww >= 256u) continue;
                acc += Fs[ly + kh * dil][lx + kw * dil] * Wsm[kh * 5 + kw];
            }
        }
        long oidx = (long)bc * HW + h * 256 + w;
        if (!fuse_gelu) {
            Out[oidx] = acc;
        } else {
            float ge = 0.5f * acc * (1.f + erff(acc * 0.70710678118654752f));
            Out[oidx] = ge * cav + g_out[oidx];
        }
    }
}

// ---------------- launcher ----------------
extern "C" void kernel_launch(void* const* d_in, const int* in_sizes, int n_in,
                              void* d_out, int out_size)
{
    const float* x    = (const float*)d_in[0];
    const float* cg   = (const float*)d_in[1];
    const float* gu   = (const float*)d_in[2];
    const float* pv_w = (const float*)d_in[3];
    const float* pv_b = (const float*)d_in[4];
    const float* pq_w = (const float*)d_in[5];
    const float* pq_b = (const float*)d_in[6];
    const float* pk_w = (const float*)d_in[7];
    const float* pk_b = (const float*)d_in[8];
    const float* cs1_w = (const float*)d_in[9];
    const float* cs1_b = (const float*)d_in[10];
    const float* cs2_w = (const float*)d_in[11];
    const float* cs2_b = (const float*)d_in[12];
    const float* cs3_w = (const float*)d_in[13];
    const float* cs3_b = (const float*)d_in[14];
    const float* po_w  = (const float*)d_in[15];
    const float* po_b  = (const float*)d_in[16];
    const float* rin_w = (const float*)d_in[17];
    const float* rin_b = (const float*)d_in[18];
    const float* roff1_w = (const float*)d_in[19];
    const float* roff1_b = (const float*)d_in[20];
    const float* roff2_w = (const float*)d_in[21];
    const float* roff2_b = (const float*)d_in[22];
    const float* rm1_w = (const float*)d_in[23];
    const float* rm1_b = (const float*)d_in[24];
    const float* rm2_w = (const float*)d_in[25];
    const float* rm2_b = (const float*)d_in[26];
    const float* rca_w = (const float*)d_in[27];
    const float* rca_b = (const float*)d_in[28];
    const float* rsa_w = (const float*)d_in[29];
    const float* rsa_b = (const float*)d_in[30];
    float* out = (float*)d_out;

    float *p_cond, *p_f, *p_out, *p_b1, *p_b2;
    __nv_bfloat16 *p_whi, *p_wlo, *p_whi2, *p_wlo2, *p_whi3, *p_wlo3;
    __nv_bfloat16 *p_whi4, *p_wlo4, *p_whi5, *p_wlo5, *p_rwhi, *p_rwlo;
    cudaGetSymbolAddress((void**)&p_cond, g_cond);
    cudaGetSymbolAddress((void**)&p_f,    g_f);
    cudaGetSymbolAddress((void**)&p_out,  g_out);
    cudaGetSymbolAddress((void**)&p_b1,   g_b1);
    cudaGetSymbolAddress((void**)&p_b2,   g_b2);
    cudaGetSymbolAddress((void**)&p_whi,  g_whi);
    cudaGetSymbolAddress((void**)&p_wlo,  g_wlo);
    cudaGetSymbolAddress((void**)&p_whi2, g_whi2);
    cudaGetSymbolAddress((void**)&p_wlo2, g_wlo2);
    cudaGetSymbolAddress((void**)&p_whi3, g_whi3);
    cudaGetSymbolAddress((void**)&p_wlo3, g_wlo3);
    cudaGetSymbolAddress((void**)&p_whi4, g_whi4);
    cudaGetSymbolAddress((void**)&p_wlo4, g_wlo4);
    cudaGetSymbolAddress((void**)&p_whi5, g_whi5);
    cudaGetSymbolAddress((void**)&p_wlo5, g_wlo5);
    cudaGetSymbolAddress((void**)&p_rwhi, g_rwhi);
    cudaGetSymbolAddress((void**)&p_rwlo, g_rwlo);

    static int attr_set = 0;
    if (!attr_set) {
        cudaFuncSetAttribute(conv_mma, cudaFuncAttributeMaxDynamicSharedMemorySize,
                             CONV_SMEM);
        cudaFuncSetAttribute(rin_mma, cudaFuncAttributeMaxDynamicSharedMemorySize,
                             RIN_SMEM);
        cudaFuncSetAttribute(convqk_mma, cudaFuncAttributeMaxDynamicSharedMemorySize,
                             QK_SMEM);
        cudaFuncSetAttribute(attn_kernel, cudaFuncAttributeMaxDynamicSharedMemorySize,
                             AT_SMEM);
        attr_set = 1;
    }

    dim3 blk(256);
    int cgrid = (BATCH * HW / 128) / TPB_CONV;   // 1024

    // 0. all weight pre-splits up front
    w_prep<<<64, blk>>>(pv_w, p_whi5, p_wlo5);
    w_prep<<<64, blk>>>(pq_w, p_whi,  p_wlo);
    w_prep<<<64, blk>>>(pk_w, p_whi2, p_wlo2);
    w_prep<<<64, blk>>>(cs1_w, p_whi3, p_wlo3);
    w_prep<<<64, blk>>>(po_w,  p_whi4, p_wlo4);
    w_prep_rin<<<16, blk>>>(rin_w, p_rwhi, p_rwlo);

    // 1. v = pv conv -> cond channels 0..127 (HMMA)
    conv_mma<<<cgrid, blk, CONV_SMEM>>>(x, (long)CH * HW, p_whi5, p_wlo5, pv_b,
                                        p_cond, (long)CD * HW);
    // 2. f = leaky(rin conv)
    rin_mma<<<cgrid, blk, RIN_SMEM>>>(p_cond, cg, rin_w, p_rwhi, p_rwlo,
                                      rin_b, p_f);
    // 3. offsets + fused channel-mean, then remaining predictor stats
    roff_kernel<<<BATCH * HW / 256, blk>>>(roff1_w, roff1_b, roff2_w, roff2_b);
    fm_kernel<<<BATCH * C4, blk>>>();
    ca_kernel<<<1, BATCH * CH>>>(rca_w, rca_b);
    sa_kernel<<<BATCH * HW / 256, blk>>>(rsa_w, rsa_b);
    // 4. hard mask
    mask_kernel<<<BATCH * NWIN, blk>>>(rm1_w, rm1_b, rm2_w, rm2_b, gu);
    // 5. fused warp + q/k projections (emit packed bf16 hi/lo)
    convqk_mma<<<cgrid, blk, QK_SMEM>>>(x, p_whi, p_wlo, p_whi2, p_wlo2,
                                        pq_b, pk_b);
    // 6. fused attention
    attn_kernel<<<dim3(4, BATCH * NWIN), blk, AT_SMEM>>>();
    // 7. cs chain
    conv_mma<<<cgrid, blk, CONV_SMEM>>>(p_out, (long)CH * HW, p_whi3, p_wlo3, cs1_b,
                                        p_b1, (long)CH * HW);
    dw5_tiled<<<BATCH * CH * 64, blk>>>(p_b1, cs2_w, cs2_b, p_b2, 1, 0);
    dw5_tiled<<<BATCH * CH * 64, blk>>>(p_b2, cs3_w, cs3_b, p_b1, 3, 1);
    // 8. final projection
    conv_mma<<<cgrid, blk, CONV_SMEM>>>(p_b1, (long)CH * HW, p_whi4, p_wlo4, po_b,
                                        out, (long)CH * HW);
    (void)in_sizes; (void)n_in; (void)out_size;
}